// round 10
// baseline (speedup 1.0000x reference)
#include <cuda_runtime.h>
#include <cuda_bf16.h>
#include <math.h>
#include <stdint.h>

// Problem constants
#define B_ 4
#define T_ 1024
#define D_ 1024
#define H_ 16
#define S_ 64
#define HID_ 3072
#define BT_ (B_*T_)

// ---------------- scratch (device globals; no allocation allowed) -----------
__device__ unsigned g_amax[8];
__device__ float g_suq[S_*S_];
__device__ float g_svq[S_*S_];
__device__ __align__(16) __nv_bfloat16 g_Mt[2*64*64];   // M^T hi | lo
__device__ float g_qkv[BT_*3*D_];    // reused as 6 bf16 planes [4096][1024]
__device__ float g_x1[BT_*D_];
__device__ float g_h[BT_*HID_];
__device__ __nv_bfloat16 g_as[BT_*3*D_];
__device__ __nv_bfloat16 g_acts[(size_t)BT_*2*HID_];
__device__ __nv_bfloat16 g_wqkvs[3*D_*2*D_];            // int codes [k|k]
__device__ __nv_bfloat16 g_wos[D_*2*D_];
__device__ __nv_bfloat16 g_wups[HID_*2*D_];
__device__ __nv_bfloat16 g_wdns[(size_t)D_*2*HID_];

// ---------------- inline PTX helpers ----------------------------------------
__device__ __forceinline__ uint32_t smem_u32(const void* p) {
    uint32_t a;
    asm("{ .reg .u64 t; cvta.to.shared.u64 t, %1; cvt.u32.u64 %0, t; }"
        : "=r"(a) : "l"(p));
    return a;
}
__device__ __forceinline__ void cpa16(uint32_t dst, const void* src) {
    asm volatile("cp.async.cg.shared.global [%0], [%1], 16;"
                 :: "r"(dst), "l"(src) : "memory");
}
#define CP_COMMIT() asm volatile("cp.async.commit_group;" ::: "memory")
#define CP_WAIT(n)  asm volatile("cp.async.wait_group %0;" :: "n"(n) : "memory")

__device__ __forceinline__ void ldm4(uint32_t* r, uint32_t addr) {
    asm volatile("ldmatrix.sync.aligned.m8n8.x4.shared.b16 {%0,%1,%2,%3}, [%4];"
                 : "=r"(r[0]), "=r"(r[1]), "=r"(r[2]), "=r"(r[3]) : "r"(addr));
}
__device__ __forceinline__ void ldm4t(uint32_t* r, uint32_t addr) {
    asm volatile("ldmatrix.sync.aligned.m8n8.x4.trans.shared.b16 {%0,%1,%2,%3}, [%4];"
                 : "=r"(r[0]), "=r"(r[1]), "=r"(r[2]), "=r"(r[3]) : "r"(addr));
}
__device__ __forceinline__ void mma16816(float* c, const uint32_t* a,
                                         uint32_t b0, uint32_t b1) {
    asm volatile(
        "mma.sync.aligned.m16n8k16.row.col.f32.bf16.bf16.f32 "
        "{%0,%1,%2,%3}, {%4,%5,%6,%7}, {%8,%9}, {%0,%1,%2,%3};"
        : "+f"(c[0]), "+f"(c[1]), "+f"(c[2]), "+f"(c[3])
        : "r"(a[0]), "r"(a[1]), "r"(a[2]), "r"(a[3]), "r"(b0), "r"(b1));
}

#define SWZB(r, c) (((r) << 6) + (((((c) ^ ((r) >> 1))) & 3) << 4))
#define SWZ128(r, cw) (((r) << 7) + ((((cw) ^ ((r) & 7))) << 4))

__device__ __forceinline__ void packhl(uint32_t& dh, uint32_t& dl,
                                       float x0, float x1) {
    __nv_bfloat16 h0 = __float2bfloat16(x0), h1 = __float2bfloat16(x1);
    dh = ((uint32_t)__bfloat16_as_ushort(h1) << 16) | __bfloat16_as_ushort(h0);
    __nv_bfloat16 g0 = __float2bfloat16(x0 - __bfloat162float(h0));
    __nv_bfloat16 g1 = __float2bfloat16(x1 - __bfloat162float(h1));
    dl = ((uint32_t)__bfloat16_as_ushort(g1) << 16) | __bfloat16_as_ushort(g0);
}

// ---------------- fused quantization -----------------------------------------
__global__ void k_absmax_all(const float* wq, const float* wk, const float* wv,
                             const float* wo, const float* su, const float* sv,
                             const float* wup, const float* wdn) {
    int slot = blockIdx.y;
    const float* w;
    int n;
    switch (slot) {
        case 0: w = wq; n = D_*D_; break;
        case 1: w = wk; n = D_*D_; break;
        case 2: w = wv; n = D_*D_; break;
        case 3: w = wo; n = D_*D_; break;
        case 4: w = su; n = S_*S_; break;
        case 5: w = sv; n = S_*S_; break;
        case 6: w = wup; n = HID_*D_; break;
        default: w = wdn; n = D_*HID_; break;
    }
    float m = 0.f;
    for (int i = blockIdx.x * blockDim.x + threadIdx.x; i < n;
         i += gridDim.x * blockDim.x)
        m = fmaxf(m, fabsf(w[i]));
#pragma unroll
    for (int o = 16; o; o >>= 1)
        m = fmaxf(m, __shfl_xor_sync(0xffffffffu, m, o));
    __shared__ float sm[8];
    int wid = threadIdx.x >> 5;
    if ((threadIdx.x & 31) == 0) sm[wid] = m;
    __syncthreads();
    if (threadIdx.x == 0) {
        for (int i = 1; i < 8; i++) m = fmaxf(m, sm[i]);
        atomicMax(&g_amax[slot], __float_as_uint(m));
    }
}

__global__ void k_quant_all(const float* wq, const float* wk, const float* wv,
                            const float* wo, const float* su, const float* sv,
                            const float* wup, const float* wdn) {
    int slot = blockIdx.y;
    const float* src;
    float* fdst = nullptr;
    __nv_bfloat16* idst = nullptr;
    int n, K = 0;
    switch (slot) {
        case 0: src = wq; idst = g_wqkvs; n = D_*D_; K = D_; break;
        case 1: src = wk; idst = g_wqkvs + (size_t)1024 * 2048; n = D_*D_; K = D_; break;
        case 2: src = wv; idst = g_wqkvs + (size_t)2048 * 2048; n = D_*D_; K = D_; break;
        case 3: src = wo; idst = g_wos; n = D_*D_; K = D_; break;
        case 4: src = su; fdst = g_suq; n = S_*S_; break;
        case 5: src = sv; fdst = g_svq; n = S_*S_; break;
        case 6: src = wup; idst = g_wups; n = HID_*D_; K = D_; break;
        default: src = wdn; idst = g_wdns; n = D_*HID_; K = HID_; break;
    }
    float s = __uint_as_float(g_amax[slot]) / 31.0f + 1e-8f;
    for (int i = blockIdx.x * blockDim.x + threadIdx.x; i < n;
         i += gridDim.x * blockDim.x) {
        float q = rintf(src[i] / s);
        q = fminf(fmaxf(q, -31.f), 31.f);
        if (fdst) {
            fdst[i] = q * s;
        } else {
            int r = i / K, c = i - r * K;
            __nv_bfloat16 kq = __float2bfloat16(q);
            idst[(size_t)r * 2 * K + c] = kq;
            idst[(size_t)r * 2 * K + K + c] = kq;
        }
    }
}

// ---------------- stalk product: Mt[n][k] = sum_a sv_q[a][n] * su_q[a][k] ----
__global__ void k_stalkM() {
    int idx = blockIdx.x * 256 + threadIdx.x;
    int n = idx >> 6, k = idx & 63;
    float acc = 0.f;
#pragma unroll 8
    for (int a = 0; a < 64; a++)
        acc += g_svq[a * 64 + n] * g_suq[a * 64 + k];
    __nv_bfloat16 hi = __float2bfloat16(acc);
    g_Mt[idx] = hi;
    g_Mt[4096 + idx] = __float2bfloat16(acc - __bfloat162float(hi));
}

// ---------------- Q' = Q @ M, in-place on Q planes ---------------------------
// grid (32 rowblocks, 16 heads), 256 threads; smem: Qh 16K | Ql 16K | Mth 8K | Mtl 8K
#define QP_SMEM 49152

__global__ __launch_bounds__(256, 2)
void k_qprime(__nv_bfloat16* QS) {
    extern __shared__ __align__(16) char sm[];
    uint32_t smb = smem_u32(sm);
    int rows = blockIdx.x * 128, h = blockIdx.y;
    int tid = threadIdx.x, wid = tid >> 5, lane = tid & 31;
    const size_t PL = (size_t)4096 * 1024;
    int colb = h * 64;

    for (int e = tid; e < 2048; e += 256) {
        int pl = e >> 10;
        int r = (e >> 3) & 127, cw = e & 7;
        cpa16(smb + pl * 16384 + SWZ128(r, cw),
              QS + pl * PL + (size_t)(rows + r) * 1024 + colb + cw * 8);
    }
    for (int e = tid; e < 1024; e += 256) {
        int pl = e >> 9;
        int r = (e >> 3) & 63, cw = e & 7;
        cpa16(smb + 32768 + pl * 8192 + SWZ128(r, cw),
              g_Mt + pl * 4096 + r * 64 + cw * 8);
    }
    CP_COMMIT();
    CP_WAIT(0);
    __syncthreads();

    uint32_t ah[4][4], al[4][4];
    int arow = wid * 16 + (lane & 15);
    int khalf = lane >> 4;
#pragma unroll
    for (int kc = 0; kc < 4; kc++) {
        uint32_t ad = SWZ128(arow, kc * 2 + khalf);
        ldm4(ah[kc], smb + ad);
        ldm4(al[kc], smb + 16384 + ad);
    }
    float cq[8][4];
#pragma unroll
    for (int i = 0; i < 8; i++)
#pragma unroll
        for (int j = 0; j < 4; j++) cq[i][j] = 0.f;
    int brow = ((lane >> 4) << 3) + (lane & 7);
    int bhalf = (lane >> 3) & 1;
#pragma unroll
    for (int kc = 0; kc < 4; kc++) {
#pragma unroll
        for (int nf2 = 0; nf2 < 4; nf2++) {
            uint32_t bh[4], bl[4];
            uint32_t ad = SWZ128(nf2 * 16 + brow, kc * 2 + bhalf);
            ldm4(bh, smb + 32768 + ad);
            ldm4(bl, smb + 40960 + ad);
            mma16816(cq[nf2 * 2], ah[kc], bh[0], bh[1]);
            mma16816(cq[nf2 * 2], ah[kc], bl[0], bl[1]);
            mma16816(cq[nf2 * 2], al[kc], bh[0], bh[1]);
            mma16816(cq[nf2 * 2 + 1], ah[kc], bh[2], bh[3]);
            mma16816(cq[nf2 * 2 + 1], ah[kc], bl[2], bl[3]);
            mma16816(cq[nf2 * 2 + 1], al[kc], bh[2], bh[3]);
        }
    }
    int lg = lane >> 2, lt = lane & 3;
    int row0 = rows + wid * 16 + lg;
#pragma unroll
    for (int nf = 0; nf < 8; nf++) {
        int col = colb + nf * 8 + 2 * lt;
        uint32_t h01, l01, h23, l23;
        packhl(h01, l01, cq[nf][0], cq[nf][1]);
        packhl(h23, l23, cq[nf][2], cq[nf][3]);
        size_t o0 = (size_t)row0 * 1024 + col;
        size_t o1 = (size_t)(row0 + 8) * 1024 + col;
        *(uint32_t*)(QS + o0) = h01;
        *(uint32_t*)(QS + PL + o0) = l01;
        *(uint32_t*)(QS + o1) = h23;
        *(uint32_t*)(QS + PL + o1) = l23;
    }
}

// ---------------- layernorm (+silu) fused with A-side split -----------------
__global__ void k_ln(const float* __restrict__ x, const float* __restrict__ g,
                     const float* __restrict__ bb, __nv_bfloat16* __restrict__ out,
                     int n, int do_silu, int zflag) {
    extern __shared__ float row[];
    int r = blockIdx.x;
    int tid = threadIdx.x;
    if (zflag && r == 0 && tid < 8) g_amax[tid] = 0u;
    const float* xr = x + (size_t)r * n;
    float s = 0.f, s2 = 0.f;
    for (int i = tid; i < n; i += blockDim.x) {
        float v = xr[i];
        row[i] = v;
        s += v;
        s2 += v * v;
    }
#pragma unroll
    for (int o = 16; o; o >>= 1) {
        s += __shfl_xor_sync(0xffffffffu, s, o);
        s2 += __shfl_xor_sync(0xffffffffu, s2, o);
    }
    __shared__ float rs[8], rs2[8];
    __shared__ float mu_s, inv_s;
    int wid = tid >> 5;
    if ((tid & 31) == 0) { rs[wid] = s; rs2[wid] = s2; }
    __syncthreads();
    if (tid == 0) {
        float S = 0.f, S2 = 0.f;
        int nw = blockDim.x >> 5;
        for (int i = 0; i < nw; i++) { S += rs[i]; S2 += rs2[i]; }
        float mu = S / n;
        float var = S2 / n - mu * mu;
        mu_s = mu;
        inv_s = rsqrtf(var + 1e-5f);
    }
    __syncthreads();
    float mu = mu_s, inv = inv_s;
    __nv_bfloat16* orow = out + (size_t)r * 2 * n;
    for (int i = tid; i < n; i += blockDim.x) {
        float y = (row[i] - mu) * inv * g[i] + bb[i];
        if (do_silu) y = y / (1.0f + __expf(-y));
        __nv_bfloat16 hi = __float2bfloat16(y);
        __nv_bfloat16 lo = __float2bfloat16(y - __bfloat162float(hi));
        orow[i] = hi;
        orow[n + i] = lo;
    }
}

// ---------------- HMMA GEMM ---------------------------------------------------
// mode 0 plain / 1 +residual / 2 SO(2) / 3 bf16 hi-lo 6-plane QKV writer
#define STG 4
#define STG_BYTES 16384

__global__ __launch_bounds__(256, 2)
void k_mma_gemm(const __nv_bfloat16* __restrict__ A,
                const __nv_bfloat16* __restrict__ Bm,
                float* __restrict__ C, const float* __restrict__ R,
                const float* __restrict__ theta, int KK, int N, int mode,
                int slot) {
    extern __shared__ __align__(128) char smraw[];
    uint32_t smb = smem_u32(smraw);
    int tid = threadIdx.x;
    int wid = tid >> 5, lane = tid & 31;
    int wm = wid >> 2, wn = wid & 3;
    int m0 = wm * 64, n0 = wn * 32;
    int bm = blockIdx.y * 128;
    int bn = blockIdx.x * 128;

    float acc[16][4];
#pragma unroll
    for (int i = 0; i < 16; i++)
#pragma unroll
        for (int j = 0; j < 4; j++) acc[i][j] = 0.f;

    const int NC = KK >> 5;
    int r0a = tid >> 2;
    int c0a = tid & 3;
#pragma unroll
    for (int s = 0; s < STG - 1; s++) {
        uint32_t ab = smb + s * STG_BYTES;
        int kof = s << 5;
#pragma unroll
        for (int half = 0; half < 2; half++) {
            int r = r0a + half * 64;
            cpa16(ab + SWZB(r, c0a), A + (size_t)(bm + r) * KK + kof + c0a * 8);
            cpa16(ab + 8192 + SWZB(r, c0a),
                  Bm + (size_t)(bn + r) * KK + kof + c0a * 8);
        }
        CP_COMMIT();
    }

    for (int kc = 0; kc < NC; kc++) {
        CP_WAIT(STG - 2);
        __syncthreads();
        int nk = kc + STG - 1;
        if (nk < NC) {
            uint32_t ab = smb + (nk % STG) * STG_BYTES;
            int kof = nk << 5;
#pragma unroll
            for (int half = 0; half < 2; half++) {
                int r = r0a + half * 64;
                cpa16(ab + SWZB(r, c0a),
                      A + (size_t)(bm + r) * KK + kof + c0a * 8);
                cpa16(ab + 8192 + SWZB(r, c0a),
                      Bm + (size_t)(bn + r) * KK + kof + c0a * 8);
            }
        }
        CP_COMMIT();

        uint32_t ab = smb + (kc % STG) * STG_BYTES;
        uint32_t bb = ab + 8192;
#pragma unroll
        for (int ks = 0; ks < 2; ks++) {
            uint32_t af[4][4];
            int arow = m0 + (lane & 15);
            int ac = ks * 2 + (lane >> 4);
#pragma unroll
            for (int mt = 0; mt < 4; mt++)
                ldm4(af[mt], ab + SWZB(arow + mt * 16, ac));
            uint32_t bf[2][4];
            int brow = n0 + ((lane >> 4) << 3) + (lane & 7);
            int bc = ks * 2 + ((lane >> 3) & 1);
#pragma unroll
            for (int nt2 = 0; nt2 < 2; nt2++)
                ldm4(bf[nt2], bb + SWZB(brow + nt2 * 16, bc));
#pragma unroll
            for (int mt = 0; mt < 4; mt++)
#pragma unroll
                for (int nt = 0; nt < 4; nt++)
                    mma16816(acc[mt * 4 + nt], af[mt],
                             bf[nt >> 1][(nt & 1) * 2],
                             bf[nt >> 1][(nt & 1) * 2 + 1]);
        }
    }

    float scl = 1.0f;
    if (slot >= 0)
        scl = __uint_as_float(g_amax[slot]) / 31.0f + 1e-8f;
    float s3[3] = {scl, scl, scl};
    if (mode == 3) {
#pragma unroll
        for (int s = 0; s < 3; s++)
            s3[s] = __uint_as_float(g_amax[s]) / 31.0f + 1e-8f;
    }
    int lg = lane >> 2, lt = lane & 3;
#pragma unroll
    for (int mt = 0; mt < 4; mt++) {
#pragma unroll
        for (int nt = 0; nt < 4; nt++) {
            float* cf = acc[mt * 4 + nt];
            int row0 = bm + m0 + mt * 16 + lg;
            int col = bn + n0 + nt * 8 + lt * 2;
            float sc2 = (mode == 3) ? s3[col >> 10] : scl;
            float v0 = cf[0] * sc2, v1 = cf[1] * sc2;
            float v2 = cf[2] * sc2, v3 = cf[3] * sc2;
            if (mode == 3) {
                __nv_bfloat16* P = (__nv_bfloat16*)C;
                int seg = col >> 10, c = col & 1023;
                size_t PL = (size_t)4096 * 1024;
                uint32_t h01, l01, h23, l23;
                packhl(h01, l01, v0, v1);
                packhl(h23, l23, v2, v3);
                size_t o0 = (size_t)row0 * 1024 + c;
                size_t o1 = (size_t)(row0 + 8) * 1024 + c;
                *(uint32_t*)(P + 2 * seg * PL + o0) = h01;
                *(uint32_t*)(P + (2 * seg + 1) * PL + o0) = l01;
                *(uint32_t*)(P + 2 * seg * PL + o1) = h23;
                *(uint32_t*)(P + (2 * seg + 1) * PL + o1) = l23;
                continue;
            }
            if (mode == 2) {
                float cs, sn;
                __sincosf(theta[col >> 1], &sn, &cs);
                float a0 = v0, b0 = v1, a1 = v2, b1 = v3;
                v0 = cs * a0 - sn * b0;
                v1 = sn * a0 + cs * b0;
                v2 = cs * a1 - sn * b1;
                v3 = sn * a1 + cs * b1;
            }
            if (mode == 1) {
                float2 r0 = *(const float2*)(R + (size_t)row0 * N + col);
                float2 r1 = *(const float2*)(R + (size_t)(row0 + 8) * N + col);
                v0 += r0.x; v1 += r0.y; v2 += r1.x; v3 += r1.y;
            }
            *(float2*)(C + (size_t)row0 * N + col) = make_float2(v0, v1);
            *(float2*)(C + (size_t)(row0 + 8) * N + col) = make_float2(v2, v3);
        }
    }
}

// ---------------- tensor-core flash attention --------------------------------
// smem: Qh 0 | Ql 16K | KV stage s at 32K+s*32K | bias 96K  (100KB -> 2 CTA/SM)
#define ATTN_SMEM5 (98304 + 4096)

__global__ __launch_bounds__(256, 2)
void k_attn_tc(const __nv_bfloat16* __restrict__ QS,
               __nv_bfloat16* __restrict__ Osplit,
               const float* __restrict__ ps_ptr) {
    extern __shared__ __align__(16) char sm[];
    uint32_t smb = smem_u32(sm);
    float* bias = (float*)(sm + 98304);
    int Qt = 7 - blockIdx.x;             // big tiles first
    int h = blockIdx.y, b = blockIdx.z;
    int tid = threadIdx.x, wid = tid >> 5, lane = tid & 31;
    int lg = lane >> 2, lt = lane & 3;
    float ps = ps_ptr[0];
    for (int i = tid; i < 1024; i += 256)
        bias[i] = (i == 0) ? ps
                 : ps * fminf((float)(__ffs(i) - 1), 16.f) * 0.0625f;

    const size_t PL = (size_t)4096 * 1024;
    size_t rowbase = (size_t)b * 1024;
    int colb = h * 64;
    int q0 = Qt * 128;

    for (int e = tid; e < 2048; e += 256) {
        int pl = e >> 10;
        int r = (e >> 3) & 127, cw = e & 7;
        cpa16(smb + pl * 16384 + SWZ128(r, cw),
              QS + pl * PL + (rowbase + q0 + r) * 1024 + colb + cw * 8);
    }
    for (int e = tid; e < 2048; e += 256) {
        int sub = e >> 9;
        int r = (e >> 3) & 63, cw = e & 7;
        cpa16(smb + 32768 + sub * 8192 + SWZ128(r, cw),
              QS + (2 + sub) * PL + (rowbase + r) * 1024 + colb + cw * 8);
    }
    CP_COMMIT();

    uint32_t aqh[4][4], aql[4][4];
    float m_i[2] = {-1e30f, -1e30f}, l_i[2] = {0.f, 0.f};
    float oac[8][4];
#pragma unroll
    for (int i = 0; i < 8; i++)
#pragma unroll
        for (int j = 0; j < 4; j++) oac[i][j] = 0.f;

    int wq0 = q0 + wid * 16;
    int ntiles = (Qt + 1) * 2;

    for (int jt = 0; jt < ntiles; jt++) {
        if (jt + 1 < ntiles) {
            int k0n = (jt + 1) * 64;
            uint32_t stb = smb + 32768 + ((jt + 1) & 1) * 32768;
            for (int e = tid; e < 2048; e += 256) {
                int sub = e >> 9;
                int r = (e >> 3) & 63, cw = e & 7;
                cpa16(stb + sub * 8192 + SWZ128(r, cw),
                      QS + (2 + sub) * PL + (rowbase + k0n + r) * 1024 + colb + cw * 8);
            }
            CP_COMMIT();
            CP_WAIT(1);
        } else {
            CP_WAIT(0);
        }
        __syncthreads();
        if (jt == 0) {
            int arow = wid * 16 + (lane & 15);
            int khalf = lane >> 4;
#pragma unroll
            for (int kc = 0; kc < 4; kc++) {
                uint32_t ad = SWZ128(arow, kc * 2 + khalf);
                ldm4(aqh[kc], smb + ad);
                ldm4(aql[kc], smb + 16384 + ad);
            }
        }
        int k0 = jt * 64;
        uint32_t stb = smb + 32768 + (jt & 1) * 32768;
        if (k0 <= wq0 + 15) {
            float sc[8][4];
#pragma unroll
            for (int i = 0; i < 8; i++)
#pragma unroll
                for (int j = 0; j < 4; j++) sc[i][j] = 0.f;
            {
                int brow = ((lane >> 4) << 3) + (lane & 7);
                int bhalf = (lane >> 3) & 1;
#pragma unroll
                for (int kc = 0; kc < 4; kc++) {
#pragma unroll
                    for (int nf2 = 0; nf2 < 4; nf2++) {
                        uint32_t bh[4], bl[4];
                        uint32_t ad = SWZ128(nf2 * 16 + brow, kc * 2 + bhalf);
                        ldm4(bh, stb + ad);
                        ldm4(bl, stb + 8192 + ad);
                        mma16816(sc[nf2 * 2], aqh[kc], bh[0], bh[1]);
                        mma16816(sc[nf2 * 2], aqh[kc], bl[0], bl[1]);
                        mma16816(sc[nf2 * 2], aql[kc], bh[0], bh[1]);
                        mma16816(sc[nf2 * 2 + 1], aqh[kc], bh[2], bh[3]);
                        mma16816(sc[nf2 * 2 + 1], aqh[kc], bl[2], bl[3]);
                        mma16816(sc[nf2 * 2 + 1], aql[kc], bh[2], bh[3]);
                    }
                }
            }
            int r0t = wq0 + lg, r1t = r0t + 8;
            bool diag = (k0 + 63 > wq0);
#pragma unroll
            for (int nf = 0; nf < 8; nf++) {
                int c0 = k0 + nf * 8 + 2 * lt;
                int d00 = r0t - c0, d01 = d00 - 1;
                int d10 = r1t - c0, d11 = d10 - 1;
                if (diag) {
                    sc[nf][0] = (d00 < 0) ? -1e30f : sc[nf][0] * 0.125f + bias[d00];
                    sc[nf][1] = (d01 < 0) ? -1e30f : sc[nf][1] * 0.125f + bias[d01];
                    sc[nf][2] = (d10 < 0) ? -1e30f : sc[nf][2] * 0.125f + bias[d10];
                    sc[nf][3] = (d11 < 0) ? -1e30f : sc[nf][3] * 0.125f + bias[d11];
                } else {
                    sc[nf][0] = sc[nf][0] * 0.125f + bias[d00];
                    sc[nf][1] = sc[nf][1] * 0.125f + bias[d01];
                    sc[nf][2] = sc[nf][2] * 0.125f + bias[d10];
                    sc[nf][3] = sc[nf][3] * 0.125f + bias[d11];
                }
            }
#pragma unroll
            for (int rh = 0; rh < 2; rh++) {
                float rm = -1e30f;
#pragma unroll
                for (int nf = 0; nf < 8; nf++)
                    rm = fmaxf(rm, fmaxf(sc[nf][rh * 2], sc[nf][rh * 2 + 1]));
                rm = fmaxf(rm, __shfl_xor_sync(0xffffffffu, rm, 1));
                rm = fmaxf(rm, __shfl_xor_sync(0xffffffffu, rm, 2));
                float mnew = fmaxf(m_i[rh], rm);
                float alpha = __expf(m_i[rh] - mnew);
                m_i[rh] = mnew;
                float rsum = 0.f;
#pragma unroll
                for (int nf = 0; nf < 8; nf++) {
                    float p0 = __expf(sc[nf][rh * 2] - mnew);
                    float p1 = __expf(sc[nf][rh * 2 + 1] - mnew);
                    sc[nf][rh * 2] = p0;
                    sc[nf][rh * 2 + 1] = p1;
                    rsum += p0 + p1;
                }
                rsum += __shfl_xor_sync(0xffffffffu, rsum, 1);
                rsum += __shfl_xor_sync(0xffffffffu, rsum, 2);
                l_i[rh] = l_i[rh] * alpha + rsum;
#pragma unroll
                for (int nf = 0; nf < 8; nf++) {
                    oac[nf][rh * 2] *= alpha;
                    oac[nf][rh * 2 + 1] *= alpha;
                }
            }
            {
                int vrow = (lane & 7) + (((lane >> 3) & 1) << 3);
                int vhalf = (lane >> 4) & 1;
#pragma unroll
                for (int uk = 0; uk < 4; uk++) {
                    uint32_t ph[4], pl[4];
                    packhl(ph[0], pl[0], sc[2 * uk][0], sc[2 * uk][1]);
                    packhl(ph[1], pl[1], sc[2 * uk][2], sc[2 * uk][3]);
                    packhl(ph[2], pl[2], sc[2 * uk + 1][0], sc[2 * uk + 1][1]);
                    packhl(ph[3], pl[3], sc[2 * uk + 1][2], sc[2 * uk + 1][3]);
#pragma unroll
                    for (int sf2 = 0; sf2 < 4; sf2++) {
                        uint32_t vh[4], vl[4];
                        uint32_t ad = SWZ128(uk * 16 + vrow, sf2 * 2 + vhalf);
                        ldm4t(vh, stb + 16384 + ad);
                        ldm4t(vl, stb + 24576 + ad);
                        mma16816(oac[sf2 * 2], ph, vh[0], vh[1]);
                        mma16816(oac[sf2 * 2], ph, vl[0], vl[1]);
                        mma16816(oac[sf2 * 2], pl, vh[0], vh[1]);
                        mma16816(oac[sf2 * 2 + 1], ph, vh[2], vh[3]);
                        mma16816(oac[sf2 * 2 + 1], ph, vl[2], vl[3]);
                        mma16816(oac[sf2 * 2 + 1], pl, vh[2], vh[3]);
                    }
                }
            }
        }
        __syncthreads();
    }
#pragma unroll
    for (int rh = 0; rh < 2; rh++) {
        float inv = 1.f / l_i[rh];
        size_t orow = (rowbase + wq0 + lg + rh * 8) * 2048;
#pragma unroll
        for (int nf = 0; nf < 8; nf++) {
            float v0 = oac[nf][rh * 2] * inv;
            float v1 = oac[nf][rh * 2 + 1] * inv;
            uint32_t hp, lp;
            packhl(hp, lp, v0, v1);
            int col = h * 64 + nf * 8 + 2 * lt;
            *(uint32_t*)(Osplit + orow + col) = hp;
            *(uint32_t*)(Osplit + orow + 1024 + col) = lp;
        }
    }
}

// ---------------- host orchestration ----------------------------------------
extern "C" void kernel_launch(void* const* d_in, const int* in_sizes, int n_in,
                              void* d_out, int out_size) {
    const float* x      = (const float*)d_in[0];
    const float* wq     = (const float*)d_in[1];
    const float* wk     = (const float*)d_in[2];
    const float* wv     = (const float*)d_in[3];
    const float* wo     = (const float*)d_in[4];
    const float* su     = (const float*)d_in[5];
    const float* sv     = (const float*)d_in[6];
    const float* pscale = (const float*)d_in[7];
    const float* n1g    = (const float*)d_in[8];
    const float* n1b    = (const float*)d_in[9];
    const float* n2g    = (const float*)d_in[10];
    const float* n2b    = (const float*)d_in[11];
    const float* w_up   = (const float*)d_in[12];
    const float* w_down = (const float*)d_in[13];
    const float* theta  = (const float*)d_in[14];
    const float* mg     = (const float*)d_in[15];
    const float* mb     = (const float*)d_in[16];
    float* out = (float*)d_out;

    float *qkv, *x1, *hb;
    __nv_bfloat16 *as_, *acts, *wqkvs, *wos, *wups, *wdns;
    cudaGetSymbolAddress((void**)&qkv, g_qkv);
    cudaGetSymbolAddress((void**)&x1, g_x1);
    cudaGetSymbolAddress((void**)&hb, g_h);
    cudaGetSymbolAddress((void**)&as_, g_as);
    cudaGetSymbolAddress((void**)&acts, g_acts);
    cudaGetSymbolAddress((void**)&wqkvs, g_wqkvs);
    cudaGetSymbolAddress((void**)&wos, g_wos);
    cudaGetSymbolAddress((void**)&wups, g_wups);
    cudaGetSymbolAddress((void**)&wdns, g_wdns);

    const int GSM = STG * STG_BYTES;
    cudaFuncSetAttribute(k_attn_tc, cudaFuncAttributeMaxDynamicSharedMemorySize,
                         ATTN_SMEM5);
    cudaFuncSetAttribute(k_mma_gemm,
                         cudaFuncAttributeMaxDynamicSharedMemorySize, GSM);
    cudaFuncSetAttribute(k_qprime, cudaFuncAttributeMaxDynamicSharedMemorySize,
                         QP_SMEM);

    // 1. ln1 (also zeroes g_amax)
    k_ln<<<BT_, 256, D_ * 4>>>(x, n1g, n1b, as_, D_, 0, 1);
    // 2. absmax
    k_absmax_all<<<dim3(256, 8), 256>>>(wq, wk, wv, wo, su, sv, w_up, w_down);
    // 3. quant
    k_quant_all<<<dim3(1024, 8), 256>>>(wq, wk, wv, wo, su, sv, w_up, w_down);
    // 4. fused QKV projection  <-- profiled launch
    k_mma_gemm<<<dim3(24, 32), 256, GSM>>>(as_, wqkvs, qkv, nullptr, nullptr,
                                           2 * D_, 3 * D_, 3, -1);
    // 5. stalk product M
    k_stalkM<<<16, 256>>>();
    // 6. Q' = Q @ M in-place
    k_qprime<<<dim3(32, 16), 256, QP_SMEM>>>((__nv_bfloat16*)qkv);
    // 7. attention
    k_attn_tc<<<dim3(8, 16, 4), 256, ATTN_SMEM5>>>(
        (const __nv_bfloat16*)qkv, as_, pscale);
    // 8. output projection + residual
    k_mma_gemm<<<dim3(8, 32), 256, GSM>>>(as_, wos, x1, x, nullptr,
                                          2 * D_, D_, 1, 3);
    // 9. ln2
    k_ln<<<BT_, 256, D_ * 4>>>(x1, n2g, n2b, as_, D_, 0, 0);
    // 10. MLP up + SO(2)
    k_mma_gemm<<<dim3(24, 32), 256, GSM>>>(as_, wups, hb, nullptr, theta,
                                           2 * D_, HID_, 2, 6);
    // 11. mlp layernorm + silu
    k_ln<<<BT_, 256, HID_ * 4>>>(hb, mg, mb, acts, HID_, 1, 0);
    // 12. MLP down + residual -> out
    k_mma_gemm<<<dim3(8, 32), 256, GSM>>>(acts, wdns, out, x1, nullptr,
                                          2 * HID_, D_, 1, 7);
}

// round 11
// speedup vs baseline: 1.0586x; 1.0586x over previous
#include <cuda_runtime.h>
#include <cuda_bf16.h>
#include <math.h>
#include <stdint.h>

// Problem constants
#define B_ 4
#define T_ 1024
#define D_ 1024
#define H_ 16
#define S_ 64
#define HID_ 3072
#define BT_ (B_*T_)

// ---------------- scratch (device globals; no allocation allowed) -----------
__device__ unsigned g_amax[8];
__device__ float g_suq[S_*S_];
__device__ float g_svq[S_*S_];
__device__ __align__(16) __nv_bfloat16 g_Mt[2*64*64];   // M^T hi | lo
__device__ float g_qkv[BT_*3*D_];    // reused as 6 bf16 planes [4096][1024]
__device__ float g_x1[BT_*D_];
__device__ float g_h[BT_*HID_];
__device__ __nv_bfloat16 g_as[BT_*3*D_];
__device__ __nv_bfloat16 g_acts[(size_t)BT_*2*HID_];
__device__ __nv_bfloat16 g_wqkvs[3*D_*2*D_];            // int codes [k|k]
__device__ __nv_bfloat16 g_wos[D_*2*D_];
__device__ __nv_bfloat16 g_wups[HID_*2*D_];
__device__ __nv_bfloat16 g_wdns[(size_t)D_*2*HID_];

// ---------------- inline PTX helpers ----------------------------------------
__device__ __forceinline__ uint32_t smem_u32(const void* p) {
    uint32_t a;
    asm("{ .reg .u64 t; cvta.to.shared.u64 t, %1; cvt.u32.u64 %0, t; }"
        : "=r"(a) : "l"(p));
    return a;
}
__device__ __forceinline__ void cpa16(uint32_t dst, const void* src) {
    asm volatile("cp.async.cg.shared.global [%0], [%1], 16;"
                 :: "r"(dst), "l"(src) : "memory");
}
#define CP_COMMIT() asm volatile("cp.async.commit_group;" ::: "memory")
#define CP_WAIT(n)  asm volatile("cp.async.wait_group %0;" :: "n"(n) : "memory")

__device__ __forceinline__ void ldm4(uint32_t* r, uint32_t addr) {
    asm volatile("ldmatrix.sync.aligned.m8n8.x4.shared.b16 {%0,%1,%2,%3}, [%4];"
                 : "=r"(r[0]), "=r"(r[1]), "=r"(r[2]), "=r"(r[3]) : "r"(addr));
}
__device__ __forceinline__ void ldm4t(uint32_t* r, uint32_t addr) {
    asm volatile("ldmatrix.sync.aligned.m8n8.x4.trans.shared.b16 {%0,%1,%2,%3}, [%4];"
                 : "=r"(r[0]), "=r"(r[1]), "=r"(r[2]), "=r"(r[3]) : "r"(addr));
}
__device__ __forceinline__ void mma16816(float* c, const uint32_t* a,
                                         uint32_t b0, uint32_t b1) {
    asm volatile(
        "mma.sync.aligned.m16n8k16.row.col.f32.bf16.bf16.f32 "
        "{%0,%1,%2,%3}, {%4,%5,%6,%7}, {%8,%9}, {%0,%1,%2,%3};"
        : "+f"(c[0]), "+f"(c[1]), "+f"(c[2]), "+f"(c[3])
        : "r"(a[0]), "r"(a[1]), "r"(a[2]), "r"(a[3]), "r"(b0), "r"(b1));
}

// 128B-row swizzle: 8 chunks of 16B, chunk' = chunk ^ (row & 7)
#define SWZ128(r, cw) (((r) << 7) + ((((cw) ^ ((r) & 7))) << 4))

__device__ __forceinline__ void packhl(uint32_t& dh, uint32_t& dl,
                                       float x0, float x1) {
    __nv_bfloat16 h0 = __float2bfloat16(x0), h1 = __float2bfloat16(x1);
    dh = ((uint32_t)__bfloat16_as_ushort(h1) << 16) | __bfloat16_as_ushort(h0);
    __nv_bfloat16 g0 = __float2bfloat16(x0 - __bfloat162float(h0));
    __nv_bfloat16 g1 = __float2bfloat16(x1 - __bfloat162float(h1));
    dl = ((uint32_t)__bfloat16_as_ushort(g1) << 16) | __bfloat16_as_ushort(g0);
}

// ---------------- fused quantization -----------------------------------------
__global__ void k_absmax_all(const float* wq, const float* wk, const float* wv,
                             const float* wo, const float* su, const float* sv,
                             const float* wup, const float* wdn) {
    int slot = blockIdx.y;
    const float* w;
    int n;
    switch (slot) {
        case 0: w = wq; n = D_*D_; break;
        case 1: w = wk; n = D_*D_; break;
        case 2: w = wv; n = D_*D_; break;
        case 3: w = wo; n = D_*D_; break;
        case 4: w = su; n = S_*S_; break;
        case 5: w = sv; n = S_*S_; break;
        case 6: w = wup; n = HID_*D_; break;
        default: w = wdn; n = D_*HID_; break;
    }
    float m = 0.f;
    for (int i = blockIdx.x * blockDim.x + threadIdx.x; i < n;
         i += gridDim.x * blockDim.x)
        m = fmaxf(m, fabsf(w[i]));
#pragma unroll
    for (int o = 16; o; o >>= 1)
        m = fmaxf(m, __shfl_xor_sync(0xffffffffu, m, o));
    __shared__ float sm[8];
    int wid = threadIdx.x >> 5;
    if ((threadIdx.x & 31) == 0) sm[wid] = m;
    __syncthreads();
    if (threadIdx.x == 0) {
        for (int i = 1; i < 8; i++) m = fmaxf(m, sm[i]);
        atomicMax(&g_amax[slot], __float_as_uint(m));
    }
}

__global__ void k_quant_all(const float* wq, const float* wk, const float* wv,
                            const float* wo, const float* su, const float* sv,
                            const float* wup, const float* wdn) {
    int slot = blockIdx.y;
    const float* src;
    float* fdst = nullptr;
    __nv_bfloat16* idst = nullptr;
    int n, K = 0;
    switch (slot) {
        case 0: src = wq; idst = g_wqkvs; n = D_*D_; K = D_; break;
        case 1: src = wk; idst = g_wqkvs + (size_t)1024 * 2048; n = D_*D_; K = D_; break;
        case 2: src = wv; idst = g_wqkvs + (size_t)2048 * 2048; n = D_*D_; K = D_; break;
        case 3: src = wo; idst = g_wos; n = D_*D_; K = D_; break;
        case 4: src = su; fdst = g_suq; n = S_*S_; break;
        case 5: src = sv; fdst = g_svq; n = S_*S_; break;
        case 6: src = wup; idst = g_wups; n = HID_*D_; K = D_; break;
        default: src = wdn; idst = g_wdns; n = D_*HID_; K = HID_; break;
    }
    float s = __uint_as_float(g_amax[slot]) / 31.0f + 1e-8f;
    for (int i = blockIdx.x * blockDim.x + threadIdx.x; i < n;
         i += gridDim.x * blockDim.x) {
        float q = rintf(src[i] / s);
        q = fminf(fmaxf(q, -31.f), 31.f);
        if (fdst) {
            fdst[i] = q * s;
        } else {
            int r = i / K, c = i - r * K;
            __nv_bfloat16 kq = __float2bfloat16(q);
            idst[(size_t)r * 2 * K + c] = kq;
            idst[(size_t)r * 2 * K + K + c] = kq;
        }
    }
}

// ---------------- stalk product: Mt[n][k] = sum_a sv_q[a][n] * su_q[a][k] ----
__global__ void k_stalkM() {
    int idx = blockIdx.x * 256 + threadIdx.x;
    int n = idx >> 6, k = idx & 63;
    float acc = 0.f;
#pragma unroll 8
    for (int a = 0; a < 64; a++)
        acc += g_svq[a * 64 + n] * g_suq[a * 64 + k];
    __nv_bfloat16 hi = __float2bfloat16(acc);
    g_Mt[idx] = hi;
    g_Mt[4096 + idx] = __float2bfloat16(acc - __bfloat162float(hi));
}

// ---------------- layernorm (+silu) fused with A-side split -----------------
__global__ void k_ln(const float* __restrict__ x, const float* __restrict__ g,
                     const float* __restrict__ bb, __nv_bfloat16* __restrict__ out,
                     int n, int do_silu, int zflag) {
    extern __shared__ float row[];
    int r = blockIdx.x;
    int tid = threadIdx.x;
    if (zflag && r == 0 && tid < 8) g_amax[tid] = 0u;
    const float* xr = x + (size_t)r * n;
    float s = 0.f, s2 = 0.f;
    for (int i = tid; i < n; i += blockDim.x) {
        float v = xr[i];
        row[i] = v;
        s += v;
        s2 += v * v;
    }
#pragma unroll
    for (int o = 16; o; o >>= 1) {
        s += __shfl_xor_sync(0xffffffffu, s, o);
        s2 += __shfl_xor_sync(0xffffffffu, s2, o);
    }
    __shared__ float rs[8], rs2[8];
    __shared__ float mu_s, inv_s;
    int wid = tid >> 5;
    if ((tid & 31) == 0) { rs[wid] = s; rs2[wid] = s2; }
    __syncthreads();
    if (tid == 0) {
        float S = 0.f, S2 = 0.f;
        int nw = blockDim.x >> 5;
        for (int i = 0; i < nw; i++) { S += rs[i]; S2 += rs2[i]; }
        float mu = S / n;
        float var = S2 / n - mu * mu;
        mu_s = mu;
        inv_s = rsqrtf(var + 1e-5f);
    }
    __syncthreads();
    float mu = mu_s, inv = inv_s;
    __nv_bfloat16* orow = out + (size_t)r * 2 * n;
    for (int i = tid; i < n; i += blockDim.x) {
        float y = (row[i] - mu) * inv * g[i] + bb[i];
        if (do_silu) y = y / (1.0f + __expf(-y));
        __nv_bfloat16 hi = __float2bfloat16(y);
        __nv_bfloat16 lo = __float2bfloat16(y - __bfloat162float(hi));
        orow[i] = hi;
        orow[n + i] = lo;
    }
}

// ---------------- HMMA GEMM (BK=64, 3-stage) ---------------------------------
// mode 0 plain / 1 +residual / 2 SO(2) / 3 bf16 hi-lo 6-plane QKV writer
#define STG 3
#define STG_BYTES 32768   // A 16KB + B 16KB (128 rows x 128B each)

__global__ __launch_bounds__(256, 2)
void k_mma_gemm(const __nv_bfloat16* __restrict__ A,
                const __nv_bfloat16* __restrict__ Bm,
                float* __restrict__ C, const float* __restrict__ R,
                const float* __restrict__ theta, int KK, int N, int mode,
                int slot) {
    extern __shared__ __align__(128) char smraw[];
    uint32_t smb = smem_u32(smraw);
    int tid = threadIdx.x;
    int wid = tid >> 5, lane = tid & 31;
    int wm = wid >> 2, wn = wid & 3;
    int m0 = wm * 64, n0 = wn * 32;
    int bm = blockIdx.y * 128;
    int bn = blockIdx.x * 128;

    float acc[16][4];
#pragma unroll
    for (int i = 0; i < 16; i++)
#pragma unroll
        for (int j = 0; j < 4; j++) acc[i][j] = 0.f;

    const int NC = KK >> 6;            // 64-wide K chunks
    // load mapping: e in [0,2048): first half A, second half B; r 0..127, cw 0..7
    int r0 = (tid >> 1) & 127;         // helper not used; explicit loop below
    (void)r0;
#pragma unroll
    for (int s = 0; s < STG - 1; s++) {
        uint32_t ab = smb + s * STG_BYTES;
        int kof = s << 6;
        for (int e = tid; e < 2048; e += 256) {
            int isB = e >> 10;
            int r = (e >> 3) & 127, cw = e & 7;
            const __nv_bfloat16* src = isB
                ? Bm + (size_t)(bn + r) * KK + kof + cw * 8
                : A + (size_t)(bm + r) * KK + kof + cw * 8;
            cpa16(ab + isB * 16384 + SWZ128(r, cw), src);
        }
        CP_COMMIT();
    }

    for (int kc = 0; kc < NC; kc++) {
        CP_WAIT(STG - 2);
        __syncthreads();
        int nk = kc + STG - 1;
        if (nk < NC) {
            uint32_t ab = smb + (nk % STG) * STG_BYTES;
            int kof = nk << 6;
            for (int e = tid; e < 2048; e += 256) {
                int isB = e >> 10;
                int r = (e >> 3) & 127, cw = e & 7;
                const __nv_bfloat16* src = isB
                    ? Bm + (size_t)(bn + r) * KK + kof + cw * 8
                    : A + (size_t)(bm + r) * KK + kof + cw * 8;
                cpa16(ab + isB * 16384 + SWZ128(r, cw), src);
            }
        }
        CP_COMMIT();

        uint32_t ab = smb + (kc % STG) * STG_BYTES;
        uint32_t bb = ab + 16384;
#pragma unroll
        for (int ks = 0; ks < 4; ks++) {
            uint32_t af[4][4];
            int arow = m0 + (lane & 15);
            int ac = ks * 2 + (lane >> 4);
#pragma unroll
            for (int mt = 0; mt < 4; mt++)
                ldm4(af[mt], ab + SWZ128(arow + mt * 16, ac));
            uint32_t bf[2][4];
            int brow = n0 + ((lane >> 4) << 3) + (lane & 7);
            int bc = ks * 2 + ((lane >> 3) & 1);
#pragma unroll
            for (int nt2 = 0; nt2 < 2; nt2++)
                ldm4(bf[nt2], bb + SWZ128(brow + nt2 * 16, bc));
#pragma unroll
            for (int mt = 0; mt < 4; mt++)
#pragma unroll
                for (int nt = 0; nt < 4; nt++)
                    mma16816(acc[mt * 4 + nt], af[mt],
                             bf[nt >> 1][(nt & 1) * 2],
                             bf[nt >> 1][(nt & 1) * 2 + 1]);
        }
    }

    float scl = 1.0f;
    if (slot >= 0)
        scl = __uint_as_float(g_amax[slot]) / 31.0f + 1e-8f;
    float s3[3] = {scl, scl, scl};
    if (mode == 3) {
#pragma unroll
        for (int s = 0; s < 3; s++)
            s3[s] = __uint_as_float(g_amax[s]) / 31.0f + 1e-8f;
    }
    int lg = lane >> 2, lt = lane & 3;
#pragma unroll
    for (int mt = 0; mt < 4; mt++) {
#pragma unroll
        for (int nt = 0; nt < 4; nt++) {
            float* cf = acc[mt * 4 + nt];
            int row0 = bm + m0 + mt * 16 + lg;
            int col = bn + n0 + nt * 8 + lt * 2;
            float sc2 = (mode == 3) ? s3[col >> 10] : scl;
            float v0 = cf[0] * sc2, v1 = cf[1] * sc2;
            float v2 = cf[2] * sc2, v3 = cf[3] * sc2;
            if (mode == 3) {
                __nv_bfloat16* P = (__nv_bfloat16*)C;
                int seg = col >> 10, c = col & 1023;
                size_t PL = (size_t)4096 * 1024;
                uint32_t h01, l01, h23, l23;
                packhl(h01, l01, v0, v1);
                packhl(h23, l23, v2, v3);
                size_t o0 = (size_t)row0 * 1024 + c;
                size_t o1 = (size_t)(row0 + 8) * 1024 + c;
                *(uint32_t*)(P + 2 * seg * PL + o0) = h01;
                *(uint32_t*)(P + (2 * seg + 1) * PL + o0) = l01;
                *(uint32_t*)(P + 2 * seg * PL + o1) = h23;
                *(uint32_t*)(P + (2 * seg + 1) * PL + o1) = l23;
                continue;
            }
            if (mode == 2) {
                float cs, sn;
                __sincosf(theta[col >> 1], &sn, &cs);
                float a0 = v0, b0 = v1, a1 = v2, b1 = v3;
                v0 = cs * a0 - sn * b0;
                v1 = sn * a0 + cs * b0;
                v2 = cs * a1 - sn * b1;
                v3 = sn * a1 + cs * b1;
            }
            if (mode == 1) {
                float2 r0v = *(const float2*)(R + (size_t)row0 * N + col);
                float2 r1v = *(const float2*)(R + (size_t)(row0 + 8) * N + col);
                v0 += r0v.x; v1 += r0v.y; v2 += r1v.x; v3 += r1v.y;
            }
            *(float2*)(C + (size_t)row0 * N + col) = make_float2(v0, v1);
            *(float2*)(C + (size_t)(row0 + 8) * N + col) = make_float2(v2, v3);
        }
    }
}

// ---------------- tensor-core flash attention (R9 form) ----------------------
// smem: Qh 0 | Ql 16K | Mth 32K | Mtl 40K | KV stage s at 48K+s*32K | bias 112K
#define ATTN_SMEM4 (114688 + 4096)

__global__ __launch_bounds__(256, 1)
void k_attn_tc(const __nv_bfloat16* __restrict__ QS,
               __nv_bfloat16* __restrict__ Osplit,
               const float* __restrict__ ps_ptr) {
    extern __shared__ __align__(16) char sm[];
    uint32_t smb = smem_u32(sm);
    float* bias = (float*)(sm + 114688);
    int Qt = blockIdx.x, h = blockIdx.y, b = blockIdx.z;
    int tid = threadIdx.x, wid = tid >> 5, lane = tid & 31;
    int lg = lane >> 2, lt = lane & 3;
    float ps = ps_ptr[0];
    for (int i = tid; i < 1024; i += 256)
        bias[i] = (i == 0) ? ps
                 : ps * fminf((float)(__ffs(i) - 1), 16.f) * 0.0625f;

    const size_t PL = (size_t)4096 * 1024;
    size_t rowbase = (size_t)b * 1024;
    int colb = h * 64;
    int q0 = Qt * 128;

    for (int e = tid; e < 2048; e += 256) {
        int pl = e >> 10;
        int r = (e >> 3) & 127, cw = e & 7;
        cpa16(smb + pl * 16384 + SWZ128(r, cw),
              QS + pl * PL + (rowbase + q0 + r) * 1024 + colb + cw * 8);
    }
    for (int e = tid; e < 1024; e += 256) {
        int pl = e >> 9;
        int r = (e >> 3) & 63, cw = e & 7;
        cpa16(smb + 32768 + pl * 8192 + SWZ128(r, cw),
              g_Mt + pl * 4096 + r * 64 + cw * 8);
    }
    for (int e = tid; e < 2048; e += 256) {
        int sub = e >> 9;
        int r = (e >> 3) & 63, cw = e & 7;
        cpa16(smb + 49152 + sub * 8192 + SWZ128(r, cw),
              QS + (2 + sub) * PL + (rowbase + r) * 1024 + colb + cw * 8);
    }
    CP_COMMIT();

    uint32_t aqh[4][4], aql[4][4];
    float m_i[2] = {-1e30f, -1e30f}, l_i[2] = {0.f, 0.f};
    float oac[8][4];
#pragma unroll
    for (int i = 0; i < 8; i++)
#pragma unroll
        for (int j = 0; j < 4; j++) oac[i][j] = 0.f;

    int wq0 = q0 + wid * 16;
    int ntiles = (Qt + 1) * 2;

    for (int jt = 0; jt < ntiles; jt++) {
        if (jt + 1 < ntiles) {
            int k0n = (jt + 1) * 64;
            uint32_t stb = smb + 49152 + ((jt + 1) & 1) * 32768;
            for (int e = tid; e < 2048; e += 256) {
                int sub = e >> 9;
                int r = (e >> 3) & 63, cw = e & 7;
                cpa16(stb + sub * 8192 + SWZ128(r, cw),
                      QS + (2 + sub) * PL + (rowbase + k0n + r) * 1024 + colb + cw * 8);
            }
            CP_COMMIT();
            CP_WAIT(1);
        } else {
            CP_WAIT(0);
        }
        __syncthreads();
        if (jt == 0) {
            // Q' = Q @ M (3-term), repack C-frags as A-frags hi/lo
            uint32_t ah[4][4], al[4][4];
            int arow = wid * 16 + (lane & 15);
            int khalf = lane >> 4;
#pragma unroll
            for (int kc = 0; kc < 4; kc++) {
                uint32_t ad = SWZ128(arow, kc * 2 + khalf);
                ldm4(ah[kc], smb + ad);
                ldm4(al[kc], smb + 16384 + ad);
            }
            float cq[8][4];
#pragma unroll
            for (int i = 0; i < 8; i++)
#pragma unroll
                for (int j = 0; j < 4; j++) cq[i][j] = 0.f;
            int brow = ((lane >> 4) << 3) + (lane & 7);
            int bhalf = (lane >> 3) & 1;
#pragma unroll
            for (int kc = 0; kc < 4; kc++) {
#pragma unroll
                for (int nf2 = 0; nf2 < 4; nf2++) {
                    uint32_t bh[4], bl[4];
                    uint32_t ad = SWZ128(nf2 * 16 + brow, kc * 2 + bhalf);
                    ldm4(bh, smb + 32768 + ad);
                    ldm4(bl, smb + 40960 + ad);
                    mma16816(cq[nf2 * 2], ah[kc], bh[0], bh[1]);
                    mma16816(cq[nf2 * 2], ah[kc], bl[0], bl[1]);
                    mma16816(cq[nf2 * 2], al[kc], bh[0], bh[1]);
                    mma16816(cq[nf2 * 2 + 1], ah[kc], bh[2], bh[3]);
                    mma16816(cq[nf2 * 2 + 1], ah[kc], bl[2], bl[3]);
                    mma16816(cq[nf2 * 2 + 1], al[kc], bh[2], bh[3]);
                }
            }
#pragma unroll
            for (int kc = 0; kc < 4; kc++) {
                packhl(aqh[kc][0], aql[kc][0], cq[2 * kc][0], cq[2 * kc][1]);
                packhl(aqh[kc][1], aql[kc][1], cq[2 * kc][2], cq[2 * kc][3]);
                packhl(aqh[kc][2], aql[kc][2], cq[2 * kc + 1][0], cq[2 * kc + 1][1]);
                packhl(aqh[kc][3], aql[kc][3], cq[2 * kc + 1][2], cq[2 * kc + 1][3]);
            }
        }
        int k0 = jt * 64;
        uint32_t stb = smb + 49152 + (jt & 1) * 32768;
        if (k0 <= wq0 + 15) {
            float sc[8][4];
#pragma unroll
            for (int i = 0; i < 8; i++)
#pragma unroll
                for (int j = 0; j < 4; j++) sc[i][j] = 0.f;
            {
                int brow = ((lane >> 4) << 3) + (lane & 7);
                int bhalf = (lane >> 3) & 1;
#pragma unroll
                for (int kc = 0; kc < 4; kc++) {
#pragma unroll
                    for (int nf2 = 0; nf2 < 4; nf2++) {
                        uint32_t bh[4], bl[4];
                        uint32_t ad = SWZ128(nf2 * 16 + brow, kc * 2 + bhalf);
                        ldm4(bh, stb + ad);
                        ldm4(bl, stb + 8192 + ad);
                        mma16816(sc[nf2 * 2], aqh[kc], bh[0], bh[1]);
                        mma16816(sc[nf2 * 2], aqh[kc], bl[0], bl[1]);
                        mma16816(sc[nf2 * 2], aql[kc], bh[0], bh[1]);
                        mma16816(sc[nf2 * 2 + 1], aqh[kc], bh[2], bh[3]);
                        mma16816(sc[nf2 * 2 + 1], aqh[kc], bl[2], bl[3]);
                        mma16816(sc[nf2 * 2 + 1], aql[kc], bh[2], bh[3]);
                    }
                }
            }
            int r0t = wq0 + lg, r1t = r0t + 8;
            bool diag = (k0 + 63 > wq0);
#pragma unroll
            for (int nf = 0; nf < 8; nf++) {
                int c0 = k0 + nf * 8 + 2 * lt;
                int d00 = r0t - c0, d01 = d00 - 1;
                int d10 = r1t - c0, d11 = d10 - 1;
                if (diag) {
                    sc[nf][0] = (d00 < 0) ? -1e30f : sc[nf][0] * 0.125f + bias[d00];
                    sc[nf][1] = (d01 < 0) ? -1e30f : sc[nf][1] * 0.125f + bias[d01];
                    sc[nf][2] = (d10 < 0) ? -1e30f : sc[nf][2] * 0.125f + bias[d10];
                    sc[nf][3] = (d11 < 0) ? -1e30f : sc[nf][3] * 0.125f + bias[d11];
                } else {
                    sc[nf][0] = sc[nf][0] * 0.125f + bias[d00];
                    sc[nf][1] = sc[nf][1] * 0.125f + bias[d01];
                    sc[nf][2] = sc[nf][2] * 0.125f + bias[d10];
                    sc[nf][3] = sc[nf][3] * 0.125f + bias[d11];
                }
            }
#pragma unroll
            for (int rh = 0; rh < 2; rh++) {
                float rm = -1e30f;
#pragma unroll
                for (int nf = 0; nf < 8; nf++)
                    rm = fmaxf(rm, fmaxf(sc[nf][rh * 2], sc[nf][rh * 2 + 1]));
                rm = fmaxf(rm, __shfl_xor_sync(0xffffffffu, rm, 1));
                rm = fmaxf(rm, __shfl_xor_sync(0xffffffffu, rm, 2));
                float mnew = fmaxf(m_i[rh], rm);
                float alpha = __expf(m_i[rh] - mnew);
                m_i[rh] = mnew;
                float rsum = 0.f;
#pragma unroll
                for (int nf = 0; nf < 8; nf++) {
                    float p0 = __expf(sc[nf][rh * 2] - mnew);
                    float p1 = __expf(sc[nf][rh * 2 + 1] - mnew);
                    sc[nf][rh * 2] = p0;
                    sc[nf][rh * 2 + 1] = p1;
                    rsum += p0 + p1;
                }
                rsum += __shfl_xor_sync(0xffffffffu, rsum, 1);
                rsum += __shfl_xor_sync(0xffffffffu, rsum, 2);
                l_i[rh] = l_i[rh] * alpha + rsum;
#pragma unroll
                for (int nf = 0; nf < 8; nf++) {
                    oac[nf][rh * 2] *= alpha;
                    oac[nf][rh * 2 + 1] *= alpha;
                }
            }
            {
                int vrow = (lane & 7) + (((lane >> 3) & 1) << 3);
                int vhalf = (lane >> 4) & 1;
#pragma unroll
                for (int uk = 0; uk < 4; uk++) {
                    uint32_t ph[4], pl[4];
                    packhl(ph[0], pl[0], sc[2 * uk][0], sc[2 * uk][1]);
                    packhl(ph[1], pl[1], sc[2 * uk][2], sc[2 * uk][3]);
                    packhl(ph[2], pl[2], sc[2 * uk + 1][0], sc[2 * uk + 1][1]);
                    packhl(ph[3], pl[3], sc[2 * uk + 1][2], sc[2 * uk + 1][3]);
#pragma unroll
                    for (int sf2 = 0; sf2 < 4; sf2++) {
                        uint32_t vh[4], vl[4];
                        uint32_t ad = SWZ128(uk * 16 + vrow, sf2 * 2 + vhalf);
                        ldm4t(vh, stb + 16384 + ad);
                        ldm4t(vl, stb + 24576 + ad);
                        mma16816(oac[sf2 * 2], ph, vh[0], vh[1]);
                        mma16816(oac[sf2 * 2], ph, vl[0], vl[1]);
                        mma16816(oac[sf2 * 2], pl, vh[0], vh[1]);
                        mma16816(oac[sf2 * 2 + 1], ph, vh[2], vh[3]);
                        mma16816(oac[sf2 * 2 + 1], ph, vl[2], vl[3]);
                        mma16816(oac[sf2 * 2 + 1], pl, vh[2], vh[3]);
                    }
                }
            }
        }
        __syncthreads();
    }
#pragma unroll
    for (int rh = 0; rh < 2; rh++) {
        float inv = 1.f / l_i[rh];
        size_t orow = (rowbase + wq0 + lg + rh * 8) * 2048;
#pragma unroll
        for (int nf = 0; nf < 8; nf++) {
            float v0 = oac[nf][rh * 2] * inv;
            float v1 = oac[nf][rh * 2 + 1] * inv;
            uint32_t hp, lp;
            packhl(hp, lp, v0, v1);
            int col = h * 64 + nf * 8 + 2 * lt;
            *(uint32_t*)(Osplit + orow + col) = hp;
            *(uint32_t*)(Osplit + orow + 1024 + col) = lp;
        }
    }
}

// ---------------- host orchestration ----------------------------------------
extern "C" void kernel_launch(void* const* d_in, const int* in_sizes, int n_in,
                              void* d_out, int out_size) {
    const float* x      = (const float*)d_in[0];
    const float* wq     = (const float*)d_in[1];
    const float* wk     = (const float*)d_in[2];
    const float* wv     = (const float*)d_in[3];
    const float* wo     = (const float*)d_in[4];
    const float* su     = (const float*)d_in[5];
    const float* sv     = (const float*)d_in[6];
    const float* pscale = (const float*)d_in[7];
    const float* n1g    = (const float*)d_in[8];
    const float* n1b    = (const float*)d_in[9];
    const float* n2g    = (const float*)d_in[10];
    const float* n2b    = (const float*)d_in[11];
    const float* w_up   = (const float*)d_in[12];
    const float* w_down = (const float*)d_in[13];
    const float* theta  = (const float*)d_in[14];
    const float* mg     = (const float*)d_in[15];
    const float* mb     = (const float*)d_in[16];
    float* out = (float*)d_out;

    float *qkv, *x1, *hb;
    __nv_bfloat16 *as_, *acts, *wqkvs, *wos, *wups, *wdns;
    cudaGetSymbolAddress((void**)&qkv, g_qkv);
    cudaGetSymbolAddress((void**)&x1, g_x1);
    cudaGetSymbolAddress((void**)&hb, g_h);
    cudaGetSymbolAddress((void**)&as_, g_as);
    cudaGetSymbolAddress((void**)&acts, g_acts);
    cudaGetSymbolAddress((void**)&wqkvs, g_wqkvs);
    cudaGetSymbolAddress((void**)&wos, g_wos);
    cudaGetSymbolAddress((void**)&wups, g_wups);
    cudaGetSymbolAddress((void**)&wdns, g_wdns);

    const int GSM = STG * STG_BYTES;   // 98304
    cudaFuncSetAttribute(k_attn_tc, cudaFuncAttributeMaxDynamicSharedMemorySize,
                         ATTN_SMEM4);
    cudaFuncSetAttribute(k_mma_gemm,
                         cudaFuncAttributeMaxDynamicSharedMemorySize, GSM);

    // 1. ln1 (also zeroes g_amax)
    k_ln<<<BT_, 256, D_ * 4>>>(x, n1g, n1b, as_, D_, 0, 1);
    // 2. absmax
    k_absmax_all<<<dim3(256, 8), 256>>>(wq, wk, wv, wo, su, sv, w_up, w_down);
    // 3. quant
    k_quant_all<<<dim3(1024, 8), 256>>>(wq, wk, wv, wo, su, sv, w_up, w_down);
    // 4. fused QKV projection  <-- profiled launch
    k_mma_gemm<<<dim3(24, 32), 256, GSM>>>(as_, wqkvs, qkv, nullptr, nullptr,
                                           2 * D_, 3 * D_, 3, -1);
    // 5. stalk product M
    k_stalkM<<<16, 256>>>();
    // 6. attention (in-kernel Q' = Q@M)
    k_attn_tc<<<dim3(8, 16, 4), 256, ATTN_SMEM4>>>(
        (const __nv_bfloat16*)qkv, as_, pscale);
    // 7. output projection + residual
    k_mma_gemm<<<dim3(8, 32), 256, GSM>>>(as_, wos, x1, x, nullptr,
                                          2 * D_, D_, 1, 3);
    // 8. ln2
    k_ln<<<BT_, 256, D_ * 4>>>(x1, n2g, n2b, as_, D_, 0, 0);
    // 9. MLP up + SO(2)
    k_mma_gemm<<<dim3(24, 32), 256, GSM>>>(as_, wups, hb, nullptr, theta,
                                           2 * D_, HID_, 2, 6);
    // 10. mlp layernorm + silu
    k_ln<<<BT_, 256, HID_ * 4>>>(hb, mg, mb, acts, HID_, 1, 0);
    // 11. MLP down + residual -> out
    k_mma_gemm<<<dim3(8, 32), 256, GSM>>>(acts, wdns, out, x1, nullptr,
                                          2 * HID_, D_, 1, 7);
}

// round 12
// speedup vs baseline: 1.0875x; 1.0273x over previous
#include <cuda_runtime.h>
#include <cuda_bf16.h>
#include <math.h>
#include <stdint.h>

// Problem constants
#define B_ 4
#define T_ 1024
#define D_ 1024
#define H_ 16
#define S_ 64
#define HID_ 3072
#define BT_ (B_*T_)

// ---------------- scratch (device globals; no allocation allowed) -----------
__device__ unsigned g_amax[8];
__device__ float g_suq[S_*S_];
__device__ float g_svq[S_*S_];
__device__ __align__(16) __nv_bfloat16 g_Mt[2*64*64];   // M^T hi | lo
__device__ float g_qkv[BT_*3*D_];    // reused as 6 bf16 planes [4096][1024]
__device__ float g_x1[BT_*D_];
__device__ float g_h[BT_*HID_];
__device__ __nv_bfloat16 g_as[BT_*3*D_];
__device__ __nv_bfloat16 g_acts[(size_t)BT_*2*HID_];
__device__ __nv_bfloat16 g_wqkvs[3*D_*2*D_];            // int codes [k|k]
__device__ __nv_bfloat16 g_wos[D_*2*D_];
__device__ __nv_bfloat16 g_wups[HID_*2*D_];
__device__ __nv_bfloat16 g_wdns[(size_t)D_*2*HID_];

// ---------------- inline PTX helpers ----------------------------------------
__device__ __forceinline__ uint32_t smem_u32(const void* p) {
    uint32_t a;
    asm("{ .reg .u64 t; cvta.to.shared.u64 t, %1; cvt.u32.u64 %0, t; }"
        : "=r"(a) : "l"(p));
    return a;
}
__device__ __forceinline__ void cpa16(uint32_t dst, const void* src) {
    asm volatile("cp.async.cg.shared.global [%0], [%1], 16;"
                 :: "r"(dst), "l"(src) : "memory");
}
#define CP_COMMIT() asm volatile("cp.async.commit_group;" ::: "memory")
#define CP_WAIT(n)  asm volatile("cp.async.wait_group %0;" :: "n"(n) : "memory")

__device__ __forceinline__ void ldm4(uint32_t* r, uint32_t addr) {
    asm volatile("ldmatrix.sync.aligned.m8n8.x4.shared.b16 {%0,%1,%2,%3}, [%4];"
                 : "=r"(r[0]), "=r"(r[1]), "=r"(r[2]), "=r"(r[3]) : "r"(addr));
}
__device__ __forceinline__ void ldm4t(uint32_t* r, uint32_t addr) {
    asm volatile("ldmatrix.sync.aligned.m8n8.x4.trans.shared.b16 {%0,%1,%2,%3}, [%4];"
                 : "=r"(r[0]), "=r"(r[1]), "=r"(r[2]), "=r"(r[3]) : "r"(addr));
}
__device__ __forceinline__ void mma16816(float* c, const uint32_t* a,
                                         uint32_t b0, uint32_t b1) {
    asm volatile(
        "mma.sync.aligned.m16n8k16.row.col.f32.bf16.bf16.f32 "
        "{%0,%1,%2,%3}, {%4,%5,%6,%7}, {%8,%9}, {%0,%1,%2,%3};"
        : "+f"(c[0]), "+f"(c[1]), "+f"(c[2]), "+f"(c[3])
        : "r"(a[0]), "r"(a[1]), "r"(a[2]), "r"(a[3]), "r"(b0), "r"(b1));
}

// 128B-row swizzle: 8 chunks of 16B, chunk' = chunk ^ (row & 7)
#define SWZ128(r, cw) (((r) << 7) + ((((cw) ^ ((r) & 7))) << 4))

__device__ __forceinline__ void packhl(uint32_t& dh, uint32_t& dl,
                                       float x0, float x1) {
    __nv_bfloat16 h0 = __float2bfloat16(x0), h1 = __float2bfloat16(x1);
    dh = ((uint32_t)__bfloat16_as_ushort(h1) << 16) | __bfloat16_as_ushort(h0);
    __nv_bfloat16 g0 = __float2bfloat16(x0 - __bfloat162float(h0));
    __nv_bfloat16 g1 = __float2bfloat16(x1 - __bfloat162float(h1));
    dl = ((uint32_t)__bfloat16_as_ushort(g1) << 16) | __bfloat16_as_ushort(g0);
}

// ---------------- fused quantization -----------------------------------------
__global__ void k_absmax_all(const float* wq, const float* wk, const float* wv,
                             const float* wo, const float* su, const float* sv,
                             const float* wup, const float* wdn) {
    int slot = blockIdx.y;
    const float* w;
    int n;
    switch (slot) {
        case 0: w = wq; n = D_*D_; break;
        case 1: w = wk; n = D_*D_; break;
        case 2: w = wv; n = D_*D_; break;
        case 3: w = wo; n = D_*D_; break;
        case 4: w = su; n = S_*S_; break;
        case 5: w = sv; n = S_*S_; break;
        case 6: w = wup; n = HID_*D_; break;
        default: w = wdn; n = D_*HID_; break;
    }
    float m = 0.f;
    for (int i = blockIdx.x * blockDim.x + threadIdx.x; i < n;
         i += gridDim.x * blockDim.x)
        m = fmaxf(m, fabsf(w[i]));
#pragma unroll
    for (int o = 16; o; o >>= 1)
        m = fmaxf(m, __shfl_xor_sync(0xffffffffu, m, o));
    __shared__ float sm[8];
    int wid = threadIdx.x >> 5;
    if ((threadIdx.x & 31) == 0) sm[wid] = m;
    __syncthreads();
    if (threadIdx.x == 0) {
        for (int i = 1; i < 8; i++) m = fmaxf(m, sm[i]);
        atomicMax(&g_amax[slot], __float_as_uint(m));
    }
}

__global__ void k_quant_all(const float* wq, const float* wk, const float* wv,
                            const float* wo, const float* su, const float* sv,
                            const float* wup, const float* wdn) {
    int slot = blockIdx.y;
    const float* src;
    float* fdst = nullptr;
    __nv_bfloat16* idst = nullptr;
    int n, K = 0;
    switch (slot) {
        case 0: src = wq; idst = g_wqkvs; n = D_*D_; K = D_; break;
        case 1: src = wk; idst = g_wqkvs + (size_t)1024 * 2048; n = D_*D_; K = D_; break;
        case 2: src = wv; idst = g_wqkvs + (size_t)2048 * 2048; n = D_*D_; K = D_; break;
        case 3: src = wo; idst = g_wos; n = D_*D_; K = D_; break;
        case 4: src = su; fdst = g_suq; n = S_*S_; break;
        case 5: src = sv; fdst = g_svq; n = S_*S_; break;
        case 6: src = wup; idst = g_wups; n = HID_*D_; K = D_; break;
        default: src = wdn; idst = g_wdns; n = D_*HID_; K = HID_; break;
    }
    float s = __uint_as_float(g_amax[slot]) / 31.0f + 1e-8f;
    for (int i = blockIdx.x * blockDim.x + threadIdx.x; i < n;
         i += gridDim.x * blockDim.x) {
        float q = rintf(src[i] / s);
        q = fminf(fmaxf(q, -31.f), 31.f);
        if (fdst) {
            fdst[i] = q * s;
        } else {
            int r = i / K, c = i - r * K;
            __nv_bfloat16 kq = __float2bfloat16(q);
            idst[(size_t)r * 2 * K + c] = kq;
            idst[(size_t)r * 2 * K + K + c] = kq;
        }
    }
}

// ---------------- stalk product: Mt[n][k] = sum_a sv_q[a][n] * su_q[a][k] ----
__global__ void k_stalkM() {
    int idx = blockIdx.x * 256 + threadIdx.x;
    int n = idx >> 6, k = idx & 63;
    float acc = 0.f;
#pragma unroll 8
    for (int a = 0; a < 64; a++)
        acc += g_svq[a * 64 + n] * g_suq[a * 64 + k];
    __nv_bfloat16 hi = __float2bfloat16(acc);
    g_Mt[idx] = hi;
    g_Mt[4096 + idx] = __float2bfloat16(acc - __bfloat162float(hi));
}

// ---------------- layernorm (+silu) fused with A-side split -----------------
__global__ void k_ln(const float* __restrict__ x, const float* __restrict__ g,
                     const float* __restrict__ bb, __nv_bfloat16* __restrict__ out,
                     int n, int do_silu, int zflag) {
    extern __shared__ float row[];
    int r = blockIdx.x;
    int tid = threadIdx.x;
    if (zflag && r == 0 && tid < 8) g_amax[tid] = 0u;
    const float* xr = x + (size_t)r * n;
    float s = 0.f, s2 = 0.f;
    for (int i = tid; i < n; i += blockDim.x) {
        float v = xr[i];
        row[i] = v;
        s += v;
        s2 += v * v;
    }
#pragma unroll
    for (int o = 16; o; o >>= 1) {
        s += __shfl_xor_sync(0xffffffffu, s, o);
        s2 += __shfl_xor_sync(0xffffffffu, s2, o);
    }
    __shared__ float rs[8], rs2[8];
    __shared__ float mu_s, inv_s;
    int wid = tid >> 5;
    if ((tid & 31) == 0) { rs[wid] = s; rs2[wid] = s2; }
    __syncthreads();
    if (tid == 0) {
        float S = 0.f, S2 = 0.f;
        int nw = blockDim.x >> 5;
        for (int i = 0; i < nw; i++) { S += rs[i]; S2 += rs2[i]; }
        float mu = S / n;
        float var = S2 / n - mu * mu;
        mu_s = mu;
        inv_s = rsqrtf(var + 1e-5f);
    }
    __syncthreads();
    float mu = mu_s, inv = inv_s;
    __nv_bfloat16* orow = out + (size_t)r * 2 * n;
    for (int i = tid; i < n; i += blockDim.x) {
        float y = (row[i] - mu) * inv * g[i] + bb[i];
        if (do_silu) y = y / (1.0f + __expf(-y));
        __nv_bfloat16 hi = __float2bfloat16(y);
        __nv_bfloat16 lo = __float2bfloat16(y - __bfloat162float(hi));
        orow[i] = hi;
        orow[n + i] = lo;
    }
}

// ---------------- HMMA GEMM (BK=64, 3-stage, strength-reduced loads) ---------
// mode 0 plain / 1 +residual / 2 SO(2) / 3 bf16 hi-lo 6-plane QKV writer
#define STG 3
#define STG_BYTES 32768   // A 16KB + B 16KB

__global__ __launch_bounds__(256, 2)
void k_mma_gemm(const __nv_bfloat16* __restrict__ A,
                const __nv_bfloat16* __restrict__ Bm,
                float* __restrict__ C, const float* __restrict__ R,
                const float* __restrict__ theta, int KK, int N, int mode,
                int slot) {
    extern __shared__ __align__(128) char smraw[];
    uint32_t smb = smem_u32(smraw);
    int tid = threadIdx.x;
    int wid = tid >> 5, lane = tid & 31;
    int wm = wid >> 2, wn = wid & 3;
    int m0 = wm * 64, n0 = wn * 32;
    int bm = blockIdx.y * 128;
    int bn = blockIdx.x * 128;

    float acc[16][4];
#pragma unroll
    for (int i = 0; i < 16; i++)
#pragma unroll
        for (int j = 0; j < 4; j++) acc[i][j] = 0.f;

    const int NC = KK >> 6;

    // strength-reduced copy addressing: thread loads rows rbase+{0,32,64,96}
    // of both A and B tiles at fixed chunk cw; swizzled chunk is i-invariant.
    int rbase = tid >> 3;                 // 0..31
    int cw = tid & 7;
    uint32_t dstb = ((uint32_t)rbase << 7) + (((cw ^ (rbase & 7))) << 4);
    const __nv_bfloat16* srcA = A + (size_t)(bm + rbase) * KK + cw * 8;
    const __nv_bfloat16* srcB = Bm + (size_t)(bn + rbase) * KK + cw * 8;
    const size_t kk32 = (size_t)32 * KK;

#pragma unroll
    for (int s = 0; s < STG - 1; s++) {
        uint32_t ab = smb + s * STG_BYTES + dstb;
        int kof = s << 6;
#pragma unroll
        for (int i = 0; i < 4; i++) {
            cpa16(ab + i * 4096, srcA + kof + i * kk32);
            cpa16(ab + 16384 + i * 4096, srcB + kof + i * kk32);
        }
        CP_COMMIT();
    }

    for (int kc = 0; kc < NC; kc++) {
        CP_WAIT(STG - 2);
        __syncthreads();
        int nk = kc + STG - 1;
        if (nk < NC) {
            uint32_t ab = smb + (nk % STG) * STG_BYTES + dstb;
            int kof = nk << 6;
#pragma unroll
            for (int i = 0; i < 4; i++) {
                cpa16(ab + i * 4096, srcA + kof + i * kk32);
                cpa16(ab + 16384 + i * 4096, srcB + kof + i * kk32);
            }
        }
        CP_COMMIT();

        uint32_t ab = smb + (kc % STG) * STG_BYTES;
        uint32_t bb = ab + 16384;
#pragma unroll
        for (int ks = 0; ks < 4; ks++) {
            uint32_t af[4][4];
            int arow = m0 + (lane & 15);
            int ac = ks * 2 + (lane >> 4);
#pragma unroll
            for (int mt = 0; mt < 4; mt++)
                ldm4(af[mt], ab + SWZ128(arow + mt * 16, ac));
            uint32_t bf[2][4];
            int brow = n0 + ((lane >> 4) << 3) + (lane & 7);
            int bc = ks * 2 + ((lane >> 3) & 1);
#pragma unroll
            for (int nt2 = 0; nt2 < 2; nt2++)
                ldm4(bf[nt2], bb + SWZ128(brow + nt2 * 16, bc));
#pragma unroll
            for (int mt = 0; mt < 4; mt++)
#pragma unroll
                for (int nt = 0; nt < 4; nt++)
                    mma16816(acc[mt * 4 + nt], af[mt],
                             bf[nt >> 1][(nt & 1) * 2],
                             bf[nt >> 1][(nt & 1) * 2 + 1]);
        }
    }

    float scl = 1.0f;
    if (slot >= 0)
        scl = __uint_as_float(g_amax[slot]) / 31.0f + 1e-8f;
    float s3[3] = {scl, scl, scl};
    if (mode == 3) {
#pragma unroll
        for (int s = 0; s < 3; s++)
            s3[s] = __uint_as_float(g_amax[s]) / 31.0f + 1e-8f;
    }
    int lg = lane >> 2, lt = lane & 3;
#pragma unroll
    for (int mt = 0; mt < 4; mt++) {
#pragma unroll
        for (int nt = 0; nt < 4; nt++) {
            float* cf = acc[mt * 4 + nt];
            int row0 = bm + m0 + mt * 16 + lg;
            int col = bn + n0 + nt * 8 + lt * 2;
            float sc2 = (mode == 3) ? s3[col >> 10] : scl;
            float v0 = cf[0] * sc2, v1 = cf[1] * sc2;
            float v2 = cf[2] * sc2, v3 = cf[3] * sc2;
            if (mode == 3) {
                __nv_bfloat16* P = (__nv_bfloat16*)C;
                int seg = col >> 10, c = col & 1023;
                size_t PL = (size_t)4096 * 1024;
                uint32_t h01, l01, h23, l23;
                packhl(h01, l01, v0, v1);
                packhl(h23, l23, v2, v3);
                size_t o0 = (size_t)row0 * 1024 + c;
                size_t o1 = (size_t)(row0 + 8) * 1024 + c;
                *(uint32_t*)(P + 2 * seg * PL + o0) = h01;
                *(uint32_t*)(P + (2 * seg + 1) * PL + o0) = l01;
                *(uint32_t*)(P + 2 * seg * PL + o1) = h23;
                *(uint32_t*)(P + (2 * seg + 1) * PL + o1) = l23;
                continue;
            }
            if (mode == 2) {
                float cs, sn;
                __sincosf(theta[col >> 1], &sn, &cs);
                float a0 = v0, b0 = v1, a1 = v2, b1 = v3;
                v0 = cs * a0 - sn * b0;
                v1 = sn * a0 + cs * b0;
                v2 = cs * a1 - sn * b1;
                v3 = sn * a1 + cs * b1;
            }
            if (mode == 1) {
                float2 r0v = *(const float2*)(R + (size_t)row0 * N + col);
                float2 r1v = *(const float2*)(R + (size_t)(row0 + 8) * N + col);
                v0 += r0v.x; v1 += r0v.y; v2 += r1v.x; v3 += r1v.y;
            }
            *(float2*)(C + (size_t)row0 * N + col) = make_float2(v0, v1);
            *(float2*)(C + (size_t)(row0 + 8) * N + col) = make_float2(v2, v3);
        }
    }
}

// ---------------- tensor-core flash attention --------------------------------
// smem: Qh 0 | Ql 16K | Mth 32K | Mtl 40K | KV stage s at 48K+s*32K | bias 112K
#define ATTN_SMEM4 (114688 + 4096)

__global__ __launch_bounds__(256, 1)
void k_attn_tc(const __nv_bfloat16* __restrict__ QS,
               __nv_bfloat16* __restrict__ Osplit,
               const float* __restrict__ ps_ptr) {
    extern __shared__ __align__(16) char sm[];
    uint32_t smb = smem_u32(sm);
    float* bias = (float*)(sm + 114688);
    int Qt = blockIdx.x, h = blockIdx.y, b = blockIdx.z;
    int tid = threadIdx.x, wid = tid >> 5, lane = tid & 31;
    int lg = lane >> 2, lt = lane & 3;
    float ps = ps_ptr[0];
    for (int i = tid; i < 1024; i += 256)
        bias[i] = (i == 0) ? ps
                 : ps * fminf((float)(__ffs(i) - 1), 16.f) * 0.0625f;

    const size_t PL = (size_t)4096 * 1024;
    size_t rowbase = (size_t)b * 1024;
    int colb = h * 64;
    int q0 = Qt * 128;

    // strength-reduced loader constants
    int rbase = tid >> 3, cw = tid & 7;
    uint32_t dstb = ((uint32_t)rbase << 7) + (((cw ^ (rbase & 7))) << 4);
    const __nv_bfloat16* kvsrc =
        QS + 2 * PL + (rowbase + rbase) * 1024 + colb + cw * 8;

    // Q planes (2 x 128 rows): pl = i>>2, r = rbase + (i&3)*32
    {
        const __nv_bfloat16* qsrc =
            QS + (rowbase + q0 + rbase) * 1024 + colb + cw * 8;
#pragma unroll
        for (int i = 0; i < 8; i++)
            cpa16(smb + dstb + (i >> 2) * 16384 + (i & 3) * 4096,
                  qsrc + (i >> 2) * PL + (size_t)(i & 3) * 32768);
    }
    // Mt planes (2 x 64 rows of 64): pl = i>>1, r = rbase + (i&1)*32
    {
        const __nv_bfloat16* msrc = g_Mt + rbase * 64 + cw * 8;
#pragma unroll
        for (int i = 0; i < 4; i++)
            cpa16(smb + 32768 + dstb + (i >> 1) * 8192 + (i & 1) * 4096,
                  msrc + (i >> 1) * 4096 + (i & 1) * 2048);
    }
    // KV tile 0: sub = i>>1, r = rbase + (i&1)*32
#pragma unroll
    for (int i = 0; i < 8; i++)
        cpa16(smb + 49152 + dstb + (i >> 1) * 8192 + (i & 1) * 4096,
              kvsrc + (i >> 1) * PL + (size_t)(i & 1) * 32768);
    CP_COMMIT();

    uint32_t aqh[4][4], aql[4][4];
    float m_i[2] = {-1e30f, -1e30f}, l_i[2] = {0.f, 0.f};
    float oac[8][4];
#pragma unroll
    for (int i = 0; i < 8; i++)
#pragma unroll
        for (int j = 0; j < 4; j++) oac[i][j] = 0.f;

    int wq0 = q0 + wid * 16;
    int ntiles = (Qt + 1) * 2;

    for (int jt = 0; jt < ntiles; jt++) {
        if (jt + 1 < ntiles) {
            size_t kof = (size_t)(jt + 1) * 64 * 1024;
            uint32_t stb = smb + 49152 + ((jt + 1) & 1) * 32768 + dstb;
#pragma unroll
            for (int i = 0; i < 8; i++)
                cpa16(stb + (i >> 1) * 8192 + (i & 1) * 4096,
                      kvsrc + kof + (i >> 1) * PL + (size_t)(i & 1) * 32768);
            CP_COMMIT();
            CP_WAIT(1);
        } else {
            CP_WAIT(0);
        }
        __syncthreads();
        if (jt == 0) {
            // Q' = Q @ M (3-term), repack C-frags as A-frags hi/lo
            uint32_t ah[4][4], al[4][4];
            int arow = wid * 16 + (lane & 15);
            int khalf = lane >> 4;
#pragma unroll
            for (int kc = 0; kc < 4; kc++) {
                uint32_t ad = SWZ128(arow, kc * 2 + khalf);
                ldm4(ah[kc], smb + ad);
                ldm4(al[kc], smb + 16384 + ad);
            }
            float cq[8][4];
#pragma unroll
            for (int i = 0; i < 8; i++)
#pragma unroll
                for (int j = 0; j < 4; j++) cq[i][j] = 0.f;
            int brow = ((lane >> 4) << 3) + (lane & 7);
            int bhalf = (lane >> 3) & 1;
#pragma unroll
            for (int kc = 0; kc < 4; kc++) {
#pragma unroll
                for (int nf2 = 0; nf2 < 4; nf2++) {
                    uint32_t bh[4], bl[4];
                    uint32_t ad = SWZ128(nf2 * 16 + brow, kc * 2 + bhalf);
                    ldm4(bh, smb + 32768 + ad);
                    ldm4(bl, smb + 40960 + ad);
                    mma16816(cq[nf2 * 2], ah[kc], bh[0], bh[1]);
                    mma16816(cq[nf2 * 2], ah[kc], bl[0], bl[1]);
                    mma16816(cq[nf2 * 2], al[kc], bh[0], bh[1]);
                    mma16816(cq[nf2 * 2 + 1], ah[kc], bh[2], bh[3]);
                    mma16816(cq[nf2 * 2 + 1], ah[kc], bl[2], bl[3]);
                    mma16816(cq[nf2 * 2 + 1], al[kc], bh[2], bh[3]);
                }
            }
#pragma unroll
            for (int kc = 0; kc < 4; kc++) {
                packhl(aqh[kc][0], aql[kc][0], cq[2 * kc][0], cq[2 * kc][1]);
                packhl(aqh[kc][1], aql[kc][1], cq[2 * kc][2], cq[2 * kc][3]);
                packhl(aqh[kc][2], aql[kc][2], cq[2 * kc + 1][0], cq[2 * kc + 1][1]);
                packhl(aqh[kc][3], aql[kc][3], cq[2 * kc + 1][2], cq[2 * kc + 1][3]);
            }
        }
        int k0 = jt * 64;
        uint32_t stb = smb + 49152 + (jt & 1) * 32768;
        if (k0 <= wq0 + 15) {
            float sc[8][4];
#pragma unroll
            for (int i = 0; i < 8; i++)
#pragma unroll
                for (int j = 0; j < 4; j++) sc[i][j] = 0.f;
            {
                int brow = ((lane >> 4) << 3) + (lane & 7);
                int bhalf = (lane >> 3) & 1;
#pragma unroll
                for (int kc = 0; kc < 4; kc++) {
#pragma unroll
                    for (int nf2 = 0; nf2 < 4; nf2++) {
                        uint32_t bh[4], bl[4];
                        uint32_t ad = SWZ128(nf2 * 16 + brow, kc * 2 + bhalf);
                        ldm4(bh, stb + ad);
                        ldm4(bl, stb + 8192 + ad);
                        mma16816(sc[nf2 * 2], aqh[kc], bh[0], bh[1]);
                        mma16816(sc[nf2 * 2], aqh[kc], bl[0], bl[1]);
                        mma16816(sc[nf2 * 2], aql[kc], bh[0], bh[1]);
                        mma16816(sc[nf2 * 2 + 1], aqh[kc], bh[2], bh[3]);
                        mma16816(sc[nf2 * 2 + 1], aqh[kc], bl[2], bl[3]);
                        mma16816(sc[nf2 * 2 + 1], aql[kc], bh[2], bh[3]);
                    }
                }
            }
            int r0t = wq0 + lg, r1t = r0t + 8;
            bool diag = (k0 + 63 > wq0);
#pragma unroll
            for (int nf = 0; nf < 8; nf++) {
                int c0 = k0 + nf * 8 + 2 * lt;
                int d00 = r0t - c0, d01 = d00 - 1;
                int d10 = r1t - c0, d11 = d10 - 1;
                if (diag) {
                    sc[nf][0] = (d00 < 0) ? -1e30f : sc[nf][0] * 0.125f + bias[d00];
                    sc[nf][1] = (d01 < 0) ? -1e30f : sc[nf][1] * 0.125f + bias[d01];
                    sc[nf][2] = (d10 < 0) ? -1e30f : sc[nf][2] * 0.125f + bias[d10];
                    sc[nf][3] = (d11 < 0) ? -1e30f : sc[nf][3] * 0.125f + bias[d11];
                } else {
                    sc[nf][0] = sc[nf][0] * 0.125f + bias[d00];
                    sc[nf][1] = sc[nf][1] * 0.125f + bias[d01];
                    sc[nf][2] = sc[nf][2] * 0.125f + bias[d10];
                    sc[nf][3] = sc[nf][3] * 0.125f + bias[d11];
                }
            }
#pragma unroll
            for (int rh = 0; rh < 2; rh++) {
                float rm = -1e30f;
#pragma unroll
                for (int nf = 0; nf < 8; nf++)
                    rm = fmaxf(rm, fmaxf(sc[nf][rh * 2], sc[nf][rh * 2 + 1]));
                rm = fmaxf(rm, __shfl_xor_sync(0xffffffffu, rm, 1));
                rm = fmaxf(rm, __shfl_xor_sync(0xffffffffu, rm, 2));
                float mnew = fmaxf(m_i[rh], rm);
                float alpha = __expf(m_i[rh] - mnew);
                m_i[rh] = mnew;
                float rsum = 0.f;
#pragma unroll
                for (int nf = 0; nf < 8; nf++) {
                    float p0 = __expf(sc[nf][rh * 2] - mnew);
                    float p1 = __expf(sc[nf][rh * 2 + 1] - mnew);
                    sc[nf][rh * 2] = p0;
                    sc[nf][rh * 2 + 1] = p1;
                    rsum += p0 + p1;
                }
                rsum += __shfl_xor_sync(0xffffffffu, rsum, 1);
                rsum += __shfl_xor_sync(0xffffffffu, rsum, 2);
                l_i[rh] = l_i[rh] * alpha + rsum;
#pragma unroll
                for (int nf = 0; nf < 8; nf++) {
                    oac[nf][rh * 2] *= alpha;
                    oac[nf][rh * 2 + 1] *= alpha;
                }
            }
            {
                int vrow = (lane & 7) + (((lane >> 3) & 1) << 3);
                int vhalf = (lane >> 4) & 1;
#pragma unroll
                for (int uk = 0; uk < 4; uk++) {
                    uint32_t ph[4], pl[4];
                    packhl(ph[0], pl[0], sc[2 * uk][0], sc[2 * uk][1]);
                    packhl(ph[1], pl[1], sc[2 * uk][2], sc[2 * uk][3]);
                    packhl(ph[2], pl[2], sc[2 * uk + 1][0], sc[2 * uk + 1][1]);
                    packhl(ph[3], pl[3], sc[2 * uk + 1][2], sc[2 * uk + 1][3]);
#pragma unroll
                    for (int sf2 = 0; sf2 < 4; sf2++) {
                        uint32_t vh[4], vl[4];
                        uint32_t ad = SWZ128(uk * 16 + vrow, sf2 * 2 + vhalf);
                        ldm4t(vh, stb + 16384 + ad);
                        ldm4t(vl, stb + 24576 + ad);
                        mma16816(oac[sf2 * 2], ph, vh[0], vh[1]);
                        mma16816(oac[sf2 * 2], ph, vl[0], vl[1]);
                        mma16816(oac[sf2 * 2], pl, vh[0], vh[1]);
                        mma16816(oac[sf2 * 2 + 1], ph, vh[2], vh[3]);
                        mma16816(oac[sf2 * 2 + 1], ph, vl[2], vl[3]);
                        mma16816(oac[sf2 * 2 + 1], pl, vh[2], vh[3]);
                    }
                }
            }
        }
        __syncthreads();
    }
#pragma unroll
    for (int rh = 0; rh < 2; rh++) {
        float inv = 1.f / l_i[rh];
        size_t orow = (rowbase + wq0 + lg + rh * 8) * 2048;
#pragma unroll
        for (int nf = 0; nf < 8; nf++) {
            float v0 = oac[nf][rh * 2] * inv;
            float v1 = oac[nf][rh * 2 + 1] * inv;
            uint32_t hp, lp;
            packhl(hp, lp, v0, v1);
            int col = h * 64 + nf * 8 + 2 * lt;
            *(uint32_t*)(Osplit + orow + col) = hp;
            *(uint32_t*)(Osplit + orow + 1024 + col) = lp;
        }
    }
}

// ---------------- host orchestration ----------------------------------------
extern "C" void kernel_launch(void* const* d_in, const int* in_sizes, int n_in,
                              void* d_out, int out_size) {
    const float* x      = (const float*)d_in[0];
    const float* wq     = (const float*)d_in[1];
    const float* wk     = (const float*)d_in[2];
    const float* wv     = (const float*)d_in[3];
    const float* wo     = (const float*)d_in[4];
    const float* su     = (const float*)d_in[5];
    const float* sv     = (const float*)d_in[6];
    const float* pscale = (const float*)d_in[7];
    const float* n1g    = (const float*)d_in[8];
    const float* n1b    = (const float*)d_in[9];
    const float* n2g    = (const float*)d_in[10];
    const float* n2b    = (const float*)d_in[11];
    const float* w_up   = (const float*)d_in[12];
    const float* w_down = (const float*)d_in[13];
    const float* theta  = (const float*)d_in[14];
    const float* mg     = (const float*)d_in[15];
    const float* mb     = (const float*)d_in[16];
    float* out = (float*)d_out;

    float *qkv, *x1, *hb;
    __nv_bfloat16 *as_, *acts, *wqkvs, *wos, *wups, *wdns;
    cudaGetSymbolAddress((void**)&qkv, g_qkv);
    cudaGetSymbolAddress((void**)&x1, g_x1);
    cudaGetSymbolAddress((void**)&hb, g_h);
    cudaGetSymbolAddress((void**)&as_, g_as);
    cudaGetSymbolAddress((void**)&acts, g_acts);
    cudaGetSymbolAddress((void**)&wqkvs, g_wqkvs);
    cudaGetSymbolAddress((void**)&wos, g_wos);
    cudaGetSymbolAddress((void**)&wups, g_wups);
    cudaGetSymbolAddress((void**)&wdns, g_wdns);

    const int GSM = STG * STG_BYTES;   // 98304
    cudaFuncSetAttribute(k_attn_tc, cudaFuncAttributeMaxDynamicSharedMemorySize,
                         ATTN_SMEM4);
    cudaFuncSetAttribute(k_mma_gemm,
                         cudaFuncAttributeMaxDynamicSharedMemorySize, GSM);

    // 1. ln1 (also zeroes g_amax)
    k_ln<<<BT_, 256, D_ * 4>>>(x, n1g, n1b, as_, D_, 0, 1);
    // 2. absmax
    k_absmax_all<<<dim3(256, 8), 256>>>(wq, wk, wv, wo, su, sv, w_up, w_down);
    // 3. quant
    k_quant_all<<<dim3(1024, 8), 256>>>(wq, wk, wv, wo, su, sv, w_up, w_down);
    // 4. fused QKV projection  <-- profiled launch
    k_mma_gemm<<<dim3(24, 32), 256, GSM>>>(as_, wqkvs, qkv, nullptr, nullptr,
                                           2 * D_, 3 * D_, 3, -1);
    // 5. stalk product M
    k_stalkM<<<16, 256>>>();
    // 6. attention (in-kernel Q' = Q@M)
    k_attn_tc<<<dim3(8, 16, 4), 256, ATTN_SMEM4>>>(
        (const __nv_bfloat16*)qkv, as_, pscale);
    // 7. output projection + residual
    k_mma_gemm<<<dim3(8, 32), 256, GSM>>>(as_, wos, x1, x, nullptr,
                                          2 * D_, D_, 1, 3);
    // 8. ln2
    k_ln<<<BT_, 256, D_ * 4>>>(x1, n2g, n2b, as_, D_, 0, 0);
    // 9. MLP up + SO(2)
    k_mma_gemm<<<dim3(24, 32), 256, GSM>>>(as_, wups, hb, nullptr, theta,
                                           2 * D_, HID_, 2, 6);
    // 10. mlp layernorm + silu
    k_ln<<<BT_, 256, HID_ * 4>>>(hb, mg, mb, acts, HID_, 1, 0);
    // 11. MLP down + residual -> out
    k_mma_gemm<<<dim3(8, 32), 256, GSM>>>(acts, wdns, out, x1, nullptr,
                                          2 * HID_, D_, 1, 7);
}

// round 13
// speedup vs baseline: 1.1882x; 1.0926x over previous
#include <cuda_runtime.h>
#include <cuda_bf16.h>
#include <math.h>
#include <stdint.h>

// Problem constants
#define B_ 4
#define T_ 1024
#define D_ 1024
#define H_ 16
#define S_ 64
#define HID_ 3072
#define BT_ (B_*T_)

// ---------------- scratch (device globals; no allocation allowed) -----------
__device__ unsigned g_amax[8];
__device__ float g_suq[S_*S_];
__device__ float g_svq[S_*S_];
__device__ __align__(16) __nv_bfloat16 g_Mt[2*64*64];   // M^T hi | lo
__device__ float g_qkv[BT_*3*D_];    // reused as 6 bf16 planes [4096][1024]
__device__ float g_x1[BT_*D_];
__device__ float g_h[BT_*HID_];
__device__ __nv_bfloat16 g_as[BT_*2*D_];                // [hi|lo] rows, 2K wide
__device__ __nv_bfloat16 g_acts[(size_t)BT_*2*HID_];
__device__ __nv_bfloat16 g_wqkvs[3*D_*D_];              // int codes, NOT duplicated
__device__ __nv_bfloat16 g_wos[D_*D_];
__device__ __nv_bfloat16 g_wups[HID_*D_];
__device__ __nv_bfloat16 g_wdns[(size_t)D_*HID_];

// ---------------- inline PTX helpers ----------------------------------------
__device__ __forceinline__ uint32_t smem_u32(const void* p) {
    uint32_t a;
    asm("{ .reg .u64 t; cvta.to.shared.u64 t, %1; cvt.u32.u64 %0, t; }"
        : "=r"(a) : "l"(p));
    return a;
}
__device__ __forceinline__ void cpa16(uint32_t dst, const void* src) {
    asm volatile("cp.async.cg.shared.global [%0], [%1], 16;"
                 :: "r"(dst), "l"(src) : "memory");
}
#define CP_COMMIT() asm volatile("cp.async.commit_group;" ::: "memory")
#define CP_WAIT(n)  asm volatile("cp.async.wait_group %0;" :: "n"(n) : "memory")

__device__ __forceinline__ void ldm4(uint32_t* r, uint32_t addr) {
    asm volatile("ldmatrix.sync.aligned.m8n8.x4.shared.b16 {%0,%1,%2,%3}, [%4];"
                 : "=r"(r[0]), "=r"(r[1]), "=r"(r[2]), "=r"(r[3]) : "r"(addr));
}
__device__ __forceinline__ void ldm4t(uint32_t* r, uint32_t addr) {
    asm volatile("ldmatrix.sync.aligned.m8n8.x4.trans.shared.b16 {%0,%1,%2,%3}, [%4];"
                 : "=r"(r[0]), "=r"(r[1]), "=r"(r[2]), "=r"(r[3]) : "r"(addr));
}
__device__ __forceinline__ void mma16816(float* c, const uint32_t* a,
                                         uint32_t b0, uint32_t b1) {
    asm volatile(
        "mma.sync.aligned.m16n8k16.row.col.f32.bf16.bf16.f32 "
        "{%0,%1,%2,%3}, {%4,%5,%6,%7}, {%8,%9}, {%0,%1,%2,%3};"
        : "+f"(c[0]), "+f"(c[1]), "+f"(c[2]), "+f"(c[3])
        : "r"(a[0]), "r"(a[1]), "r"(a[2]), "r"(a[3]), "r"(b0), "r"(b1));
}

// 128B-row swizzle: 8 chunks of 16B, chunk' = chunk ^ (row & 7)
#define SWZ128(r, cw) (((r) << 7) + ((((cw) ^ ((r) & 7))) << 4))

__device__ __forceinline__ void packhl(uint32_t& dh, uint32_t& dl,
                                       float x0, float x1) {
    __nv_bfloat16 h0 = __float2bfloat16(x0), h1 = __float2bfloat16(x1);
    dh = ((uint32_t)__bfloat16_as_ushort(h1) << 16) | __bfloat16_as_ushort(h0);
    __nv_bfloat16 g0 = __float2bfloat16(x0 - __bfloat162float(h0));
    __nv_bfloat16 g1 = __float2bfloat16(x1 - __bfloat162float(h1));
    dl = ((uint32_t)__bfloat16_as_ushort(g1) << 16) | __bfloat16_as_ushort(g0);
}

// ---------------- fused quantization -----------------------------------------
__global__ void k_absmax_all(const float* wq, const float* wk, const float* wv,
                             const float* wo, const float* su, const float* sv,
                             const float* wup, const float* wdn) {
    int slot = blockIdx.y;
    const float* w;
    int n;
    switch (slot) {
        case 0: w = wq; n = D_*D_; break;
        case 1: w = wk; n = D_*D_; break;
        case 2: w = wv; n = D_*D_; break;
        case 3: w = wo; n = D_*D_; break;
        case 4: w = su; n = S_*S_; break;
        case 5: w = sv; n = S_*S_; break;
        case 6: w = wup; n = HID_*D_; break;
        default: w = wdn; n = D_*HID_; break;
    }
    float m = 0.f;
    for (int i = blockIdx.x * blockDim.x + threadIdx.x; i < n;
         i += gridDim.x * blockDim.x)
        m = fmaxf(m, fabsf(w[i]));
#pragma unroll
    for (int o = 16; o; o >>= 1)
        m = fmaxf(m, __shfl_xor_sync(0xffffffffu, m, o));
    __shared__ float sm[8];
    int wid = threadIdx.x >> 5;
    if ((threadIdx.x & 31) == 0) sm[wid] = m;
    __syncthreads();
    if (threadIdx.x == 0) {
        for (int i = 1; i < 8; i++) m = fmaxf(m, sm[i]);
        atomicMax(&g_amax[slot], __float_as_uint(m));
    }
}

__global__ void k_quant_all(const float* wq, const float* wk, const float* wv,
                            const float* wo, const float* su, const float* sv,
                            const float* wup, const float* wdn) {
    int slot = blockIdx.y;
    const float* src;
    float* fdst = nullptr;
    __nv_bfloat16* idst = nullptr;
    int n;
    switch (slot) {
        case 0: src = wq; idst = g_wqkvs; n = D_*D_; break;
        case 1: src = wk; idst = g_wqkvs + (size_t)D_*D_; n = D_*D_; break;
        case 2: src = wv; idst = g_wqkvs + (size_t)2*D_*D_; n = D_*D_; break;
        case 3: src = wo; idst = g_wos; n = D_*D_; break;
        case 4: src = su; fdst = g_suq; n = S_*S_; break;
        case 5: src = sv; fdst = g_svq; n = S_*S_; break;
        case 6: src = wup; idst = g_wups; n = HID_*D_; break;
        default: src = wdn; idst = g_wdns; n = D_*HID_; break;
    }
    float s = __uint_as_float(g_amax[slot]) / 31.0f + 1e-8f;
    for (int i = blockIdx.x * blockDim.x + threadIdx.x; i < n;
         i += gridDim.x * blockDim.x) {
        float q = rintf(src[i] / s);
        q = fminf(fmaxf(q, -31.f), 31.f);
        if (fdst) fdst[i] = q * s;
        else      idst[i] = __float2bfloat16(q);   // exact: |q|<=31
    }
}

// ---------------- stalk product: Mt[n][k] = sum_a sv_q[a][n] * su_q[a][k] ----
__global__ void k_stalkM() {
    int idx = blockIdx.x * 256 + threadIdx.x;
    int n = idx >> 6, k = idx & 63;
    float acc = 0.f;
#pragma unroll 8
    for (int a = 0; a < 64; a++)
        acc += g_svq[a * 64 + n] * g_suq[a * 64 + k];
    __nv_bfloat16 hi = __float2bfloat16(acc);
    g_Mt[idx] = hi;
    g_Mt[4096 + idx] = __float2bfloat16(acc - __bfloat162float(hi));
}

// ---------------- layernorm (+silu) fused with A-side split -----------------
__global__ void k_ln(const float* __restrict__ x, const float* __restrict__ g,
                     const float* __restrict__ bb, __nv_bfloat16* __restrict__ out,
                     int n, int do_silu, int zflag) {
    extern __shared__ float row[];
    int r = blockIdx.x;
    int tid = threadIdx.x;
    if (zflag && r == 0 && tid < 8) g_amax[tid] = 0u;
    const float* xr = x + (size_t)r * n;
    float s = 0.f, s2 = 0.f;
    for (int i = tid; i < n; i += blockDim.x) {
        float v = xr[i];
        row[i] = v;
        s += v;
        s2 += v * v;
    }
#pragma unroll
    for (int o = 16; o; o >>= 1) {
        s += __shfl_xor_sync(0xffffffffu, s, o);
        s2 += __shfl_xor_sync(0xffffffffu, s2, o);
    }
    __shared__ float rs[8], rs2[8];
    __shared__ float mu_s, inv_s;
    int wid = tid >> 5;
    if ((tid & 31) == 0) { rs[wid] = s; rs2[wid] = s2; }
    __syncthreads();
    if (tid == 0) {
        float S = 0.f, S2 = 0.f;
        int nw = blockDim.x >> 5;
        for (int i = 0; i < nw; i++) { S += rs[i]; S2 += rs2[i]; }
        float mu = S / n;
        float var = S2 / n - mu * mu;
        mu_s = mu;
        inv_s = rsqrtf(var + 1e-5f);
    }
    __syncthreads();
    float mu = mu_s, inv = inv_s;
    __nv_bfloat16* orow = out + (size_t)r * 2 * n;
    for (int i = tid; i < n; i += blockDim.x) {
        float y = (row[i] - mu) * inv * g[i] + bb[i];
        if (do_silu) y = y / (1.0f + __expf(-y));
        __nv_bfloat16 hi = __float2bfloat16(y);
        __nv_bfloat16 lo = __float2bfloat16(y - __bfloat162float(hi));
        orow[i] = hi;
        orow[n + i] = lo;
    }
}

// ---------------- HMMA GEMM: C = (Ahi + Alo) * B^T, shared-B inner loop ------
// A rows are [hi|lo] (stride 2*KK); B rows are plain int codes (stride KK).
// stage = Ahi 16K | Alo 16K | B 16K, 2 stages, 1 barrier per 64 true-K.
// mode 0 plain / 1 +residual / 2 SO(2) / 3 bf16 hi-lo 6-plane QKV writer
#define STG 2
#define STG_BYTES 49152

__global__ __launch_bounds__(256, 2)
void k_mma_gemm(const __nv_bfloat16* __restrict__ A,
                const __nv_bfloat16* __restrict__ Bm,
                float* __restrict__ C, const float* __restrict__ R,
                const float* __restrict__ theta, int KK, int N, int mode,
                int slot) {
    extern __shared__ __align__(128) char smraw[];
    uint32_t smb = smem_u32(smraw);
    int tid = threadIdx.x;
    int wid = tid >> 5, lane = tid & 31;
    int wm = wid >> 2, wn = wid & 3;
    int m0 = wm * 64, n0 = wn * 32;
    int bm = blockIdx.y * 128;
    int bn = blockIdx.x * 128;

    float acc[16][4];
#pragma unroll
    for (int i = 0; i < 16; i++)
#pragma unroll
        for (int j = 0; j < 4; j++) acc[i][j] = 0.f;

    const int NC = KK >> 6;            // 64-wide true-K chunks

    // strength-reduced copy addressing (rows rbase+{0,32,64,96}, fixed cw)
    int rbase = tid >> 3;              // 0..31
    int cw = tid & 7;
    uint32_t dstb = ((uint32_t)rbase << 7) + (((cw ^ (rbase & 7))) << 4);
    const __nv_bfloat16* srcAh = A + (size_t)(bm + rbase) * 2 * KK + cw * 8;
    const __nv_bfloat16* srcAl = srcAh + KK;
    const __nv_bfloat16* srcB = Bm + (size_t)(bn + rbase) * KK + cw * 8;
    const size_t a32 = (size_t)32 * 2 * KK;
    const size_t b32 = (size_t)32 * KK;

    // prologue: stage 0
    {
        uint32_t ab = smb + dstb;
#pragma unroll
        for (int i = 0; i < 4; i++) {
            cpa16(ab + i * 4096, srcAh + i * a32);
            cpa16(ab + 16384 + i * 4096, srcAl + i * a32);
            cpa16(ab + 32768 + i * 4096, srcB + i * b32);
        }
        CP_COMMIT();
    }

    for (int kc = 0; kc < NC; kc++) {
        CP_WAIT(0);
        __syncthreads();
        int nk = kc + 1;
        if (nk < NC) {
            uint32_t ab = smb + (nk & 1) * STG_BYTES + dstb;
            int kof = nk << 6;
#pragma unroll
            for (int i = 0; i < 4; i++) {
                cpa16(ab + i * 4096, srcAh + kof + i * a32);
                cpa16(ab + 16384 + i * 4096, srcAl + kof + i * a32);
                cpa16(ab + 32768 + i * 4096, srcB + kof + i * b32);
            }
        }
        CP_COMMIT();

        uint32_t ab = smb + (kc & 1) * STG_BYTES;
        uint32_t bb = ab + 32768;
#pragma unroll
        for (int ks = 0; ks < 4; ks++) {
            int arow = m0 + (lane & 15);
            int ac = ks * 2 + (lane >> 4);
            uint32_t bf[2][4];
            int brow = n0 + ((lane >> 4) << 3) + (lane & 7);
            int bc = ks * 2 + ((lane >> 3) & 1);
#pragma unroll
            for (int nt2 = 0; nt2 < 2; nt2++)
                ldm4(bf[nt2], bb + SWZ128(brow + nt2 * 16, bc));
            // hi pass
            {
                uint32_t af[4][4];
#pragma unroll
                for (int mt = 0; mt < 4; mt++)
                    ldm4(af[mt], ab + SWZ128(arow + mt * 16, ac));
#pragma unroll
                for (int mt = 0; mt < 4; mt++)
#pragma unroll
                    for (int nt = 0; nt < 4; nt++)
                        mma16816(acc[mt * 4 + nt], af[mt],
                                 bf[nt >> 1][(nt & 1) * 2],
                                 bf[nt >> 1][(nt & 1) * 2 + 1]);
            }
            // lo pass (same B frags)
            {
                uint32_t af[4][4];
#pragma unroll
                for (int mt = 0; mt < 4; mt++)
                    ldm4(af[mt], ab + 16384 + SWZ128(arow + mt * 16, ac));
#pragma unroll
                for (int mt = 0; mt < 4; mt++)
#pragma unroll
                    for (int nt = 0; nt < 4; nt++)
                        mma16816(acc[mt * 4 + nt], af[mt],
                                 bf[nt >> 1][(nt & 1) * 2],
                                 bf[nt >> 1][(nt & 1) * 2 + 1]);
            }
        }
    }

    float scl = 1.0f;
    if (slot >= 0)
        scl = __uint_as_float(g_amax[slot]) / 31.0f + 1e-8f;
    float s3[3] = {scl, scl, scl};
    if (mode == 3) {
#pragma unroll
        for (int s = 0; s < 3; s++)
            s3[s] = __uint_as_float(g_amax[s]) / 31.0f + 1e-8f;
    }
    int lg = lane >> 2, lt = lane & 3;
#pragma unroll
    for (int mt = 0; mt < 4; mt++) {
#pragma unroll
        for (int nt = 0; nt < 4; nt++) {
            float* cf = acc[mt * 4 + nt];
            int row0 = bm + m0 + mt * 16 + lg;
            int col = bn + n0 + nt * 8 + lt * 2;
            float sc2 = (mode == 3) ? s3[col >> 10] : scl;
            float v0 = cf[0] * sc2, v1 = cf[1] * sc2;
            float v2 = cf[2] * sc2, v3 = cf[3] * sc2;
            if (mode == 3) {
                __nv_bfloat16* P = (__nv_bfloat16*)C;
                int seg = col >> 10, c = col & 1023;
                size_t PL = (size_t)4096 * 1024;
                uint32_t h01, l01, h23, l23;
                packhl(h01, l01, v0, v1);
                packhl(h23, l23, v2, v3);
                size_t o0 = (size_t)row0 * 1024 + c;
                size_t o1 = (size_t)(row0 + 8) * 1024 + c;
                *(uint32_t*)(P + 2 * seg * PL + o0) = h01;
                *(uint32_t*)(P + (2 * seg + 1) * PL + o0) = l01;
                *(uint32_t*)(P + 2 * seg * PL + o1) = h23;
                *(uint32_t*)(P + (2 * seg + 1) * PL + o1) = l23;
                continue;
            }
            if (mode == 2) {
                float cs, sn;
                __sincosf(theta[col >> 1], &sn, &cs);
                float a0 = v0, b0 = v1, a1 = v2, b1 = v3;
                v0 = cs * a0 - sn * b0;
                v1 = sn * a0 + cs * b0;
                v2 = cs * a1 - sn * b1;
                v3 = sn * a1 + cs * b1;
            }
            if (mode == 1) {
                float2 r0v = *(const float2*)(R + (size_t)row0 * N + col);
                float2 r1v = *(const float2*)(R + (size_t)(row0 + 8) * N + col);
                v0 += r0v.x; v1 += r0v.y; v2 += r1v.x; v3 += r1v.y;
            }
            *(float2*)(C + (size_t)row0 * N + col) = make_float2(v0, v1);
            *(float2*)(C + (size_t)(row0 + 8) * N + col) = make_float2(v2, v3);
        }
    }
}

// ---------------- tensor-core flash attention --------------------------------
// smem: Qh 0 | Ql 16K | Mth 32K | Mtl 40K | KV stage s at 48K+s*32K | bias 112K
#define ATTN_SMEM4 (114688 + 4096)

__global__ __launch_bounds__(256, 1)
void k_attn_tc(const __nv_bfloat16* __restrict__ QS,
               __nv_bfloat16* __restrict__ Osplit,
               const float* __restrict__ ps_ptr) {
    extern __shared__ __align__(16) char sm[];
    uint32_t smb = smem_u32(sm);
    float* bias = (float*)(sm + 114688);
    int Qt = blockIdx.x, h = blockIdx.y, b = blockIdx.z;
    int tid = threadIdx.x, wid = tid >> 5, lane = tid & 31;
    int lg = lane >> 2, lt = lane & 3;
    float ps = ps_ptr[0];
    for (int i = tid; i < 1024; i += 256)
        bias[i] = (i == 0) ? ps
                 : ps * fminf((float)(__ffs(i) - 1), 16.f) * 0.0625f;

    const size_t PL = (size_t)4096 * 1024;
    size_t rowbase = (size_t)b * 1024;
    int colb = h * 64;
    int q0 = Qt * 128;

    int rbase = tid >> 3, cw = tid & 7;
    uint32_t dstb = ((uint32_t)rbase << 7) + (((cw ^ (rbase & 7))) << 4);
    const __nv_bfloat16* kvsrc =
        QS + 2 * PL + (rowbase + rbase) * 1024 + colb + cw * 8;

    {
        const __nv_bfloat16* qsrc =
            QS + (rowbase + q0 + rbase) * 1024 + colb + cw * 8;
#pragma unroll
        for (int i = 0; i < 8; i++)
            cpa16(smb + dstb + (i >> 2) * 16384 + (i & 3) * 4096,
                  qsrc + (i >> 2) * PL + (size_t)(i & 3) * 32768);
    }
    {
        const __nv_bfloat16* msrc = g_Mt + rbase * 64 + cw * 8;
#pragma unroll
        for (int i = 0; i < 4; i++)
            cpa16(smb + 32768 + dstb + (i >> 1) * 8192 + (i & 1) * 4096,
                  msrc + (i >> 1) * 4096 + (i & 1) * 2048);
    }
#pragma unroll
    for (int i = 0; i < 8; i++)
        cpa16(smb + 49152 + dstb + (i >> 1) * 8192 + (i & 1) * 4096,
              kvsrc + (i >> 1) * PL + (size_t)(i & 1) * 32768);
    CP_COMMIT();

    uint32_t aqh[4][4], aql[4][4];
    float m_i[2] = {-1e30f, -1e30f}, l_i[2] = {0.f, 0.f};
    float oac[8][4];
#pragma unroll
    for (int i = 0; i < 8; i++)
#pragma unroll
        for (int j = 0; j < 4; j++) oac[i][j] = 0.f;

    int wq0 = q0 + wid * 16;
    int ntiles = (Qt + 1) * 2;

    for (int jt = 0; jt < ntiles; jt++) {
        if (jt + 1 < ntiles) {
            size_t kof = (size_t)(jt + 1) * 64 * 1024;
            uint32_t stb = smb + 49152 + ((jt + 1) & 1) * 32768 + dstb;
#pragma unroll
            for (int i = 0; i < 8; i++)
                cpa16(stb + (i >> 1) * 8192 + (i & 1) * 4096,
                      kvsrc + kof + (i >> 1) * PL + (size_t)(i & 1) * 32768);
            CP_COMMIT();
            CP_WAIT(1);
        } else {
            CP_WAIT(0);
        }
        __syncthreads();
        if (jt == 0) {
            uint32_t ah[4][4], al[4][4];
            int arow = wid * 16 + (lane & 15);
            int khalf = lane >> 4;
#pragma unroll
            for (int kc = 0; kc < 4; kc++) {
                uint32_t ad = SWZ128(arow, kc * 2 + khalf);
                ldm4(ah[kc], smb + ad);
                ldm4(al[kc], smb + 16384 + ad);
            }
            float cq[8][4];
#pragma unroll
            for (int i = 0; i < 8; i++)
#pragma unroll
                for (int j = 0; j < 4; j++) cq[i][j] = 0.f;
            int brow = ((lane >> 4) << 3) + (lane & 7);
            int bhalf = (lane >> 3) & 1;
#pragma unroll
            for (int kc = 0; kc < 4; kc++) {
#pragma unroll
                for (int nf2 = 0; nf2 < 4; nf2++) {
                    uint32_t bh[4], bl[4];
                    uint32_t ad = SWZ128(nf2 * 16 + brow, kc * 2 + bhalf);
                    ldm4(bh, smb + 32768 + ad);
                    ldm4(bl, smb + 40960 + ad);
                    mma16816(cq[nf2 * 2], ah[kc], bh[0], bh[1]);
                    mma16816(cq[nf2 * 2], ah[kc], bl[0], bl[1]);
                    mma16816(cq[nf2 * 2], al[kc], bh[0], bh[1]);
                    mma16816(cq[nf2 * 2 + 1], ah[kc], bh[2], bh[3]);
                    mma16816(cq[nf2 * 2 + 1], ah[kc], bl[2], bl[3]);
                    mma16816(cq[nf2 * 2 + 1], al[kc], bh[2], bh[3]);
                }
            }
#pragma unroll
            for (int kc = 0; kc < 4; kc++) {
                packhl(aqh[kc][0], aql[kc][0], cq[2 * kc][0], cq[2 * kc][1]);
                packhl(aqh[kc][1], aql[kc][1], cq[2 * kc][2], cq[2 * kc][3]);
                packhl(aqh[kc][2], aql[kc][2], cq[2 * kc + 1][0], cq[2 * kc + 1][1]);
                packhl(aqh[kc][3], aql[kc][3], cq[2 * kc + 1][2], cq[2 * kc + 1][3]);
            }
        }
        int k0 = jt * 64;
        uint32_t stb = smb + 49152 + (jt & 1) * 32768;
        if (k0 <= wq0 + 15) {
            float sc[8][4];
#pragma unroll
            for (int i = 0; i < 8; i++)
#pragma unroll
                for (int j = 0; j < 4; j++) sc[i][j] = 0.f;
            {
                int brow = ((lane >> 4) << 3) + (lane & 7);
                int bhalf = (lane >> 3) & 1;
#pragma unroll
                for (int kc = 0; kc < 4; kc++) {
#pragma unroll
                    for (int nf2 = 0; nf2 < 4; nf2++) {
                        uint32_t bh[4], bl[4];
                        uint32_t ad = SWZ128(nf2 * 16 + brow, kc * 2 + bhalf);
                        ldm4(bh, stb + ad);
                        ldm4(bl, stb + 8192 + ad);
                        mma16816(sc[nf2 * 2], aqh[kc], bh[0], bh[1]);
                        mma16816(sc[nf2 * 2], aqh[kc], bl[0], bl[1]);
                        mma16816(sc[nf2 * 2], aql[kc], bh[0], bh[1]);
                        mma16816(sc[nf2 * 2 + 1], aqh[kc], bh[2], bh[3]);
                        mma16816(sc[nf2 * 2 + 1], aqh[kc], bl[2], bl[3]);
                        mma16816(sc[nf2 * 2 + 1], aql[kc], bh[2], bh[3]);
                    }
                }
            }
            int r0t = wq0 + lg, r1t = r0t + 8;
            bool diag = (k0 + 63 > wq0);
#pragma unroll
            for (int nf = 0; nf < 8; nf++) {
                int c0 = k0 + nf * 8 + 2 * lt;
                int d00 = r0t - c0, d01 = d00 - 1;
                int d10 = r1t - c0, d11 = d10 - 1;
                if (diag) {
                    sc[nf][0] = (d00 < 0) ? -1e30f : sc[nf][0] * 0.125f + bias[d00];
                    sc[nf][1] = (d01 < 0) ? -1e30f : sc[nf][1] * 0.125f + bias[d01];
                    sc[nf][2] = (d10 < 0) ? -1e30f : sc[nf][2] * 0.125f + bias[d10];
                    sc[nf][3] = (d11 < 0) ? -1e30f : sc[nf][3] * 0.125f + bias[d11];
                } else {
                    sc[nf][0] = sc[nf][0] * 0.125f + bias[d00];
                    sc[nf][1] = sc[nf][1] * 0.125f + bias[d01];
                    sc[nf][2] = sc[nf][2] * 0.125f + bias[d10];
                    sc[nf][3] = sc[nf][3] * 0.125f + bias[d11];
                }
            }
#pragma unroll
            for (int rh = 0; rh < 2; rh++) {
                float rm = -1e30f;
#pragma unroll
                for (int nf = 0; nf < 8; nf++)
                    rm = fmaxf(rm, fmaxf(sc[nf][rh * 2], sc[nf][rh * 2 + 1]));
                rm = fmaxf(rm, __shfl_xor_sync(0xffffffffu, rm, 1));
                rm = fmaxf(rm, __shfl_xor_sync(0xffffffffu, rm, 2));
                float mnew = fmaxf(m_i[rh], rm);
                float alpha = __expf(m_i[rh] - mnew);
                m_i[rh] = mnew;
                float rsum = 0.f;
#pragma unroll
                for (int nf = 0; nf < 8; nf++) {
                    float p0 = __expf(sc[nf][rh * 2] - mnew);
                    float p1 = __expf(sc[nf][rh * 2 + 1] - mnew);
                    sc[nf][rh * 2] = p0;
                    sc[nf][rh * 2 + 1] = p1;
                    rsum += p0 + p1;
                }
                rsum += __shfl_xor_sync(0xffffffffu, rsum, 1);
                rsum += __shfl_xor_sync(0xffffffffu, rsum, 2);
                l_i[rh] = l_i[rh] * alpha + rsum;
#pragma unroll
                for (int nf = 0; nf < 8; nf++) {
                    oac[nf][rh * 2] *= alpha;
                    oac[nf][rh * 2 + 1] *= alpha;
                }
            }
            {
                int vrow = (lane & 7) + (((lane >> 3) & 1) << 3);
                int vhalf = (lane >> 4) & 1;
#pragma unroll
                for (int uk = 0; uk < 4; uk++) {
                    uint32_t ph[4], pl[4];
                    packhl(ph[0], pl[0], sc[2 * uk][0], sc[2 * uk][1]);
                    packhl(ph[1], pl[1], sc[2 * uk][2], sc[2 * uk][3]);
                    packhl(ph[2], pl[2], sc[2 * uk + 1][0], sc[2 * uk + 1][1]);
                    packhl(ph[3], pl[3], sc[2 * uk + 1][2], sc[2 * uk + 1][3]);
#pragma unroll
                    for (int sf2 = 0; sf2 < 4; sf2++) {
                        uint32_t vh[4], vl[4];
                        uint32_t ad = SWZ128(uk * 16 + vrow, sf2 * 2 + vhalf);
                        ldm4t(vh, stb + 16384 + ad);
                        ldm4t(vl, stb + 24576 + ad);
                        mma16816(oac[sf2 * 2], ph, vh[0], vh[1]);
                        mma16816(oac[sf2 * 2], ph, vl[0], vl[1]);
                        mma16816(oac[sf2 * 2], pl, vh[0], vh[1]);
                        mma16816(oac[sf2 * 2 + 1], ph, vh[2], vh[3]);
                        mma16816(oac[sf2 * 2 + 1], ph, vl[2], vl[3]);
                        mma16816(oac[sf2 * 2 + 1], pl, vh[2], vh[3]);
                    }
                }
            }
        }
        __syncthreads();
    }
#pragma unroll
    for (int rh = 0; rh < 2; rh++) {
        float inv = 1.f / l_i[rh];
        size_t orow = (rowbase + wq0 + lg + rh * 8) * 2048;
#pragma unroll
        for (int nf = 0; nf < 8; nf++) {
            float v0 = oac[nf][rh * 2] * inv;
            float v1 = oac[nf][rh * 2 + 1] * inv;
            uint32_t hp, lp;
            packhl(hp, lp, v0, v1);
            int col = h * 64 + nf * 8 + 2 * lt;
            *(uint32_t*)(Osplit + orow + col) = hp;
            *(uint32_t*)(Osplit + orow + 1024 + col) = lp;
        }
    }
}

// ---------------- host orchestration ----------------------------------------
extern "C" void kernel_launch(void* const* d_in, const int* in_sizes, int n_in,
                              void* d_out, int out_size) {
    const float* x      = (const float*)d_in[0];
    const float* wq     = (const float*)d_in[1];
    const float* wk     = (const float*)d_in[2];
    const float* wv     = (const float*)d_in[3];
    const float* wo     = (const float*)d_in[4];
    const float* su     = (const float*)d_in[5];
    const float* sv     = (const float*)d_in[6];
    const float* pscale = (const float*)d_in[7];
    const float* n1g    = (const float*)d_in[8];
    const float* n1b    = (const float*)d_in[9];
    const float* n2g    = (const float*)d_in[10];
    const float* n2b    = (const float*)d_in[11];
    const float* w_up   = (const float*)d_in[12];
    const float* w_down = (const float*)d_in[13];
    const float* theta  = (const float*)d_in[14];
    const float* mg     = (const float*)d_in[15];
    const float* mb     = (const float*)d_in[16];
    float* out = (float*)d_out;

    float *qkv, *x1, *hb;
    __nv_bfloat16 *as_, *acts, *wqkvs, *wos, *wups, *wdns;
    cudaGetSymbolAddress((void**)&qkv, g_qkv);
    cudaGetSymbolAddress((void**)&x1, g_x1);
    cudaGetSymbolAddress((void**)&hb, g_h);
    cudaGetSymbolAddress((void**)&as_, g_as);
    cudaGetSymbolAddress((void**)&acts, g_acts);
    cudaGetSymbolAddress((void**)&wqkvs, g_wqkvs);
    cudaGetSymbolAddress((void**)&wos, g_wos);
    cudaGetSymbolAddress((void**)&wups, g_wups);
    cudaGetSymbolAddress((void**)&wdns, g_wdns);

    const int GSM = STG * STG_BYTES;   // 98304
    cudaFuncSetAttribute(k_attn_tc, cudaFuncAttributeMaxDynamicSharedMemorySize,
                         ATTN_SMEM4);
    cudaFuncSetAttribute(k_mma_gemm,
                         cudaFuncAttributeMaxDynamicSharedMemorySize, GSM);

    // 1. ln1 (also zeroes g_amax)
    k_ln<<<BT_, 256, D_ * 4>>>(x, n1g, n1b, as_, D_, 0, 1);
    // 2. absmax
    k_absmax_all<<<dim3(256, 8), 256>>>(wq, wk, wv, wo, su, sv, w_up, w_down);
    // 3. quant (non-duplicated int codes)
    k_quant_all<<<dim3(1024, 8), 256>>>(wq, wk, wv, wo, su, sv, w_up, w_down);
    // 4. fused QKV projection  <-- profiled launch
    k_mma_gemm<<<dim3(24, 32), 256, GSM>>>(as_, wqkvs, qkv, nullptr, nullptr,
                                           D_, 3 * D_, 3, -1);
    // 5. stalk product M
    k_stalkM<<<16, 256>>>();
    // 6. attention (in-kernel Q' = Q@M)
    k_attn_tc<<<dim3(8, 16, 4), 256, ATTN_SMEM4>>>(
        (const __nv_bfloat16*)qkv, as_, pscale);
    // 7. output projection + residual
    k_mma_gemm<<<dim3(8, 32), 256, GSM>>>(as_, wos, x1, x, nullptr,
                                          D_, D_, 1, 3);
    // 8. ln2
    k_ln<<<BT_, 256, D_ * 4>>>(x1, n2g, n2b, as_, D_, 0, 0);
    // 9. MLP up + SO(2)
    k_mma_gemm<<<dim3(24, 32), 256, GSM>>>(as_, wups, hb, nullptr, theta,
                                           D_, HID_, 2, 6);
    // 10. mlp layernorm + silu
    k_ln<<<BT_, 256, HID_ * 4>>>(hb, mg, mb, acts, HID_, 1, 0);
    // 11. MLP down + residual -> out
    k_mma_gemm<<<dim3(8, 32), 256, GSM>>>(acts, wdns, out, x1, nullptr,
                                          HID_, D_, 1, 7);
}